// round 7
// baseline (speedup 1.0000x reference)
#include <cuda_runtime.h>
#include <cuda_bf16.h>
#include <math.h>
#include <stdint.h>

#define BB 64
#define SS 512
#define DD 512
#define HH 1024
#define GG 4096   // 4*HH

// ---------------------------------------------------------------------------
// Device-global scratch (no allocations allowed anywhere).
// ---------------------------------------------------------------------------
__device__ float g_gx[(size_t)BB * SS * GG];        // input projections (B*S, 4H)
__device__ float g_c[BB * HH];                      // cell state
__device__ __nv_bfloat16 g_whhi[(size_t)GG * HH];   // Wh split hi
__device__ __nv_bfloat16 g_whlo[(size_t)GG * HH];   // Wh split lo
__device__ __nv_bfloat16 g_hhi[2][BB * HH];         // h staging (parity buffers)
__device__ __nv_bfloat16 g_hlo[2][BB * HH];
__device__ int g_mma_ok = 1;                        // end-to-end verify verdict

// ---------------------------------------------------------------------------
// Portable PTX helpers
// ---------------------------------------------------------------------------
__device__ __forceinline__ uint32_t smem_u32(const void* p) {
    uint32_t a;
    asm("{ .reg .u64 t; cvta.to.shared.u64 t, %1; cvt.u32.u64 %0, t; }" : "=r"(a) : "l"(p));
    return a;
}
__device__ __forceinline__ void cpa16(uint32_t dst, const void* src) {
    asm volatile("cp.async.cg.shared.global [%0], [%1], 16;" :: "r"(dst), "l"(src));
}
#define CP_COMMIT() asm volatile("cp.async.commit_group;" ::: "memory")
#define CP_WAIT(n)  asm volatile("cp.async.wait_group %0;" :: "n"(n) : "memory")

__device__ __forceinline__ uint32_t lds32(uint32_t a) {
    uint32_t v;
    asm volatile("ld.shared.b32 %0, [%1];" : "=r"(v) : "r"(a));
    return v;
}
__device__ __forceinline__ void mma16816(float* d, const uint32_t* a, const uint32_t* b) {
    asm volatile(
        "mma.sync.aligned.m16n8k16.row.col.f32.bf16.bf16.f32 "
        "{%0,%1,%2,%3}, {%4,%5,%6,%7}, {%8,%9}, {%0,%1,%2,%3};"
        : "+f"(d[0]), "+f"(d[1]), "+f"(d[2]), "+f"(d[3])
        : "r"(a[0]), "r"(a[1]), "r"(a[2]), "r"(a[3]), "r"(b[0]), "r"(b[1]));
}

__device__ __forceinline__ float sigf(float x) { return 1.f / (1.f + __expf(-x)); }
__device__ __forceinline__ float tanhfast(float x) { return 1.f - 2.f / (__expf(2.f * x) + 1.f); }

// ---------------------------------------------------------------------------
// Split fp32 -> bf16 hi/lo
// ---------------------------------------------------------------------------
__global__ __launch_bounds__(256) void split_hl(const float* __restrict__ src,
                                                __nv_bfloat16* __restrict__ hi,
                                                __nv_bfloat16* __restrict__ lo) {
    size_t i = (size_t)blockIdx.x * 1024 + (size_t)threadIdx.x * 4;
    float4 w = *(const float4*)(src + i);
    __nv_bfloat16 h0 = __float2bfloat16(w.x), h1 = __float2bfloat16(w.y);
    __nv_bfloat16 h2 = __float2bfloat16(w.z), h3 = __float2bfloat16(w.w);
    *(__nv_bfloat162*)(hi + i)     = __nv_bfloat162(h0, h1);
    *(__nv_bfloat162*)(hi + i + 2) = __nv_bfloat162(h2, h3);
    *(__nv_bfloat162*)(lo + i) =
        __nv_bfloat162(__float2bfloat16(w.x - __bfloat162float(h0)),
                       __float2bfloat16(w.y - __bfloat162float(h1)));
    *(__nv_bfloat162*)(lo + i + 2) =
        __nv_bfloat162(__float2bfloat16(w.z - __bfloat162float(h2)),
                       __float2bfloat16(w.w - __bfloat162float(h3)));
}

// ---------------------------------------------------------------------------
// gx GEMM (fp32, PROVEN in R1)
// ---------------------------------------------------------------------------
__global__ __launch_bounds__(256) void gx_gemm(const float* __restrict__ x,
                                               const float* __restrict__ Wx,
                                               const float* __restrict__ bx,
                                               const float* __restrict__ bh) {
    __shared__ float As[16][64];
    __shared__ float Ws[16][64];
    const int tid = threadIdx.x;
    const int tx = tid & 15, ty = tid >> 4;
    const int m0 = blockIdx.y * 64, n0 = blockIdx.x * 64;
    const int lrow = tid >> 2, lk = (tid & 3) << 2;

    float acc[4][4];
#pragma unroll
    for (int i = 0; i < 4; i++)
#pragma unroll
        for (int j = 0; j < 4; j++) acc[i][j] = 0.f;

    const float* aptr = x + (size_t)(m0 + lrow) * DD + lk;
    const float* wptr = Wx + (size_t)(n0 + lrow) * DD + lk;

    for (int kt = 0; kt < DD; kt += 16) {
        float4 av = *(const float4*)(aptr + kt);
        float4 wv = *(const float4*)(wptr + kt);
        __syncthreads();
        As[lk + 0][lrow] = av.x; As[lk + 1][lrow] = av.y;
        As[lk + 2][lrow] = av.z; As[lk + 3][lrow] = av.w;
        Ws[lk + 0][lrow] = wv.x; Ws[lk + 1][lrow] = wv.y;
        Ws[lk + 2][lrow] = wv.z; Ws[lk + 3][lrow] = wv.w;
        __syncthreads();
#pragma unroll
        for (int kk = 0; kk < 16; kk++) {
            float4 a4 = *(const float4*)&As[kk][ty * 4];
            float4 b4 = *(const float4*)&Ws[kk][tx * 4];
            float a[4] = {a4.x, a4.y, a4.z, a4.w};
            float b[4] = {b4.x, b4.y, b4.z, b4.w};
#pragma unroll
            for (int i = 0; i < 4; i++)
#pragma unroll
                for (int j = 0; j < 4; j++) acc[i][j] = fmaf(a[i], b[j], acc[i][j]);
        }
    }
    const int nb = n0 + tx * 4;
    float4 bias;
    bias.x = bx[nb + 0] + bh[nb + 0];
    bias.y = bx[nb + 1] + bh[nb + 1];
    bias.z = bx[nb + 2] + bh[nb + 2];
    bias.w = bx[nb + 3] + bh[nb + 3];
#pragma unroll
    for (int i = 0; i < 4; i++) {
        const size_t m = (size_t)(m0 + ty * 4 + i);
        float4 v;
        v.x = acc[i][0] + bias.x; v.y = acc[i][1] + bias.y;
        v.z = acc[i][2] + bias.z; v.w = acc[i][3] + bias.w;
        *(float4*)&g_gx[m * GG + nb] = v;
    }
}

// ===========================================================================
// Step kernel: dual path with END-TO-END verification at t=1.
// smem buffer (27648 B each, x2), pitch 144 B:
//   Ah[32][72] @0, Al @4608, Bh[64][72] @9216, Bl @18432
// ===========================================================================
#define STEP_BUF 27648
#define STEP_SMEM (2 * STEP_BUF)

__device__ __forceinline__ void step_load(uint32_t sb, int s, int tid, int j0, int kc,
                                          const __nv_bfloat16* __restrict__ rh,
                                          const __nv_bfloat16* __restrict__ rl) {
    uint32_t ab = sb + s * STEP_BUF;
#pragma unroll
    for (int i = 0; i < 2; i++) {
        int idx = tid + 128 * i, row = idx >> 3, k8 = idx & 7;
        size_t go = ((size_t)((row >> 3) * HH + j0 + (row & 7))) * HH
                  + (size_t)kc * 64 + (size_t)k8 * 8;
        uint32_t d = ab + row * 144 + k8 * 16;
        cpa16(d, g_whhi + go);
        cpa16(d + 4608, g_whlo + go);
    }
#pragma unroll
    for (int i = 0; i < 4; i++) {
        int idx = tid + 128 * i, b = idx >> 3, k8 = idx & 7;
        size_t go = (size_t)b * HH + (size_t)kc * 64 + (size_t)k8 * 8;
        uint32_t d = ab + 9216 + b * 144 + k8 * 16;
        cpa16(d, rh + go);
        cpa16(d + 9216, rl + go);
    }
    CP_COMMIT();
}

// A frag (m16k16): a0=(g,2t..), a1=(g+8,..), a2=(g,2t+8..), a3=(g+8,2t+8..)
__device__ __forceinline__ void loadA(uint32_t base, int r0, int g, uint32_t ka,
                                      uint32_t* a) {
    a[0] = lds32(base + (r0 + g) * 144 + ka);
    a[1] = lds32(base + (r0 + g + 8) * 144 + ka);
    a[2] = lds32(base + (r0 + g) * 144 + ka + 16);
    a[3] = lds32(base + (r0 + g + 8) * 144 + ka + 16);
}
// B frag (k16n8): b0=(k=2t.., n=g), b1=(k=2t+8.., n=g); smem row = n
__device__ __forceinline__ void loadB(uint32_t base, int nb, int g, uint32_t ka,
                                      uint32_t* b) {
    b[0] = lds32(base + (nb + g) * 144 + ka);
    b[1] = lds32(base + (nb + g) * 144 + ka + 16);
}

__device__ __forceinline__ void step_compute(uint32_t sb, int s, int lane, int wid,
                                             float (&acc)[2][2][4]) {
    uint32_t ab = sb + s * STEP_BUF;
    const int g = lane >> 2, tig = lane & 3;
    const uint32_t aB = ab + 9216;
#pragma unroll
    for (int kk = 0; kk < 4; kk++) {
        const uint32_t ka = (uint32_t)((kk * 16 + 2 * tig) * 2);
        uint32_t ah0[4], ah1[4], al0[4], al1[4], bh[2][2], bl[2][2];
        loadA(ab, 0, g, ka, ah0);
        loadA(ab, 16, g, ka, ah1);
        loadA(ab + 4608, 0, g, ka, al0);
        loadA(ab + 4608, 16, g, ka, al1);
        loadB(aB, wid * 16, g, ka, bh[0]);
        loadB(aB, wid * 16 + 8, g, ka, bh[1]);
        loadB(aB + 9216, wid * 16, g, ka, bl[0]);
        loadB(aB + 9216, wid * 16 + 8, g, ka, bl[1]);
        mma16816(acc[0][0], ah0, bh[0]);  mma16816(acc[0][1], ah0, bh[1]);
        mma16816(acc[1][0], ah1, bh[0]);  mma16816(acc[1][1], ah1, bh[1]);
        mma16816(acc[0][0], ah0, bl[0]);  mma16816(acc[0][1], ah0, bl[1]);
        mma16816(acc[1][0], ah1, bl[0]);  mma16816(acc[1][1], ah1, bl[1]);
        mma16816(acc[0][0], al0, bh[0]);  mma16816(acc[0][1], al0, bh[1]);
        mma16816(acc[1][0], al1, bh[0]);  mma16816(acc[1][1], al1, bh[1]);
    }
}

__device__ __forceinline__ void lstm_elem(float* out, int t, int wf, int b, int j,
                                          float iv, float fv, float gv, float ov,
                                          __nv_bfloat16* whp, __nv_bfloat16* wlp) {
    iv = sigf(iv); fv = sigf(fv); gv = tanhfast(gv); ov = sigf(ov);
    const float cp = g_c[b * HH + j];
    const float cn = fmaf(fv, cp, iv * gv);
    const float hn = ov * tanhfast(cn);
    g_c[b * HH + j] = cn;
    out[((size_t)b * SS + t) * HH + j] = hn;
    __nv_bfloat16 hb = __float2bfloat16(hn);
    whp[b * HH + j] = hb;
    wlp[b * HH + j] = __float2bfloat16(hn - __bfloat162float(hb));
    if (wf && t == SS - 1) {
        out[(size_t)BB * SS * HH + (size_t)b * HH + j] = hn;
        out[(size_t)BB * SS * HH + (size_t)BB * HH + (size_t)b * HH + j] = cn;
    }
}

__global__ __launch_bounds__(128) void lstm_step_v7(const float* __restrict__ Wh,
                                                    float* __restrict__ out,
                                                    int t, int wf) {
    const int tid = threadIdx.x;
    const int j0 = blockIdx.x * 8;

    __nv_bfloat16* whp = g_hhi[t & 1];
    __nv_bfloat16* wlp = g_hlo[t & 1];

    if (t == 0) {
        for (int idx = tid; idx < 512; idx += 128) {
            int b = idx >> 3, jl = idx & 7, j = j0 + jl;
            size_t gb = (size_t)b * SS * GG + j;
            float iv = sigf(g_gx[gb]);
            float gv = tanhfast(g_gx[gb + 2 * HH]);
            float ov = sigf(g_gx[gb + 3 * HH]);
            float cn = iv * gv;
            float hn = ov * tanhfast(cn);
            g_c[b * HH + j] = cn;
            out[((size_t)b * SS) * HH + j] = hn;
            __nv_bfloat16 hb = __float2bfloat16(hn);
            whp[b * HH + j] = hb;
            wlp[b * HH + j] = __float2bfloat16(hn - __bfloat162float(hb));
        }
        return;
    }

    extern __shared__ __align__(128) char sm[];
    __shared__ int s_bad;
    const uint32_t sb = smem_u32(sm);
    const int wid = tid >> 5, lane = tid & 31;
    const int g = lane >> 2, q = lane & 3;

    int use_mma = (t == 1) ? 1 : *(volatile int*)&g_mma_ok;

    float acc[2][2][4];
#pragma unroll
    for (int r = 0; r < 2; r++)
#pragma unroll
        for (int c = 0; c < 2; c++)
#pragma unroll
            for (int e = 0; e < 4; e++) acc[r][c][e] = 0.f;

    if (use_mma) {
        const __nv_bfloat16* rh = g_hhi[(t - 1) & 1];
        const __nv_bfloat16* rl = g_hlo[(t - 1) & 1];

        step_load(sb, 0, tid, j0, 0, rh, rl);
#pragma unroll 1
        for (int kc = 0; kc < 16; kc++) {
            const int s = kc & 1;
            if (kc < 15) step_load(sb, s ^ 1, tid, j0, kc + 1, rh, rl);
            if (kc < 15) { CP_WAIT(1); } else { CP_WAIT(0); }
            __syncthreads();
            step_compute(sb, s, lane, wid, acc);
            __syncthreads();
        }

        if (t == 1) {
            // ===== END-TO-END verification: recompute all 16 acc elements in
            // fp32 directly from Wh (fp32) and out[t=0] (fp32). Covers split,
            // staging, cp.async addressing, pipeline, AND acc->(row,col) map.
            if (tid == 0) s_bad = 0;
            __syncthreads();
            const int j = j0 + g;
            int bc[4];
#pragma unroll
            for (int ci = 0; ci < 4; ci++)
                bc[ci] = wid * 16 + (ci >> 1) * 8 + 2 * q + (ci & 1);
            float ref[4][4];
#pragma unroll
            for (int ga = 0; ga < 4; ga++)
#pragma unroll
                for (int ci = 0; ci < 4; ci++) ref[ga][ci] = 0.f;
            const float* w0 = Wh + (size_t)(0 * HH + j) * HH;
            const float* w1 = Wh + (size_t)(1 * HH + j) * HH;
            const float* w2 = Wh + (size_t)(2 * HH + j) * HH;
            const float* w3 = Wh + (size_t)(3 * HH + j) * HH;
#pragma unroll 4
            for (int k = 0; k < HH; k++) {
                float wv[4] = {w0[k], w1[k], w2[k], w3[k]};
                float hv[4];
#pragma unroll
                for (int ci = 0; ci < 4; ci++)
                    hv[ci] = out[((size_t)bc[ci] * SS + 0) * HH + k];
#pragma unroll
                for (int ga = 0; ga < 4; ga++)
#pragma unroll
                    for (int ci = 0; ci < 4; ci++)
                        ref[ga][ci] = fmaf(wv[ga], hv[ci], ref[ga][ci]);
            }
            bool ok = true;
#pragma unroll
            for (int ga = 0; ga < 4; ga++)
#pragma unroll
                for (int ci = 0; ci < 4; ci++) {
                    float av = acc[ga >> 1][ci >> 1][((ga & 1) << 1) | (ci & 1)];
                    float rv = ref[ga][ci];
                    ok &= fabsf(av - rv) <= (2e-4f + 2e-4f * fabsf(rv));
                }
            if (!ok) s_bad = 1;
            __syncthreads();
            if (s_bad) {
                if (tid == 0) g_mma_ok = 0;   // only-zero writes: race-free
                use_mma = 0;                  // recompute this step via fallback
            }
        }
    }

    if (use_mma) {
        // mma epilogue: thread -> j = j0+g, 4 batches x 4 gates in regs.
        const int j = j0 + g;
        const int n0 = wid * 16;
#pragma unroll
        for (int c = 0; c < 2; c++)
#pragma unroll
            for (int e = 0; e < 2; e++) {
                const int b = n0 + c * 8 + 2 * q + e;
                const size_t gb = ((size_t)b * SS + t) * (size_t)GG + j;
                lstm_elem(out, t, wf, b, j,
                          acc[0][c][e]     + g_gx[gb],
                          acc[0][c][2 + e] + g_gx[gb + HH],
                          acc[1][c][e]     + g_gx[gb + 2 * HH],
                          acc[1][c][2 + e] + g_gx[gb + 3 * HH],
                          whp, wlp);
            }
    } else {
        // fp32 FFMA fallback (independent of staging/mma machinery).
        __syncthreads();
        float* Hs = (float*)sm;                 // [64][132] floats
        const int bq = tid >> 3, jl = tid & 7;
        const int j = j0 + jl;
        float facc[4][4];
#pragma unroll
        for (int a = 0; a < 4; a++)
#pragma unroll
            for (int bz = 0; bz < 4; bz++) facc[a][bz] = 0.f;

#pragma unroll 1
        for (int kt = 0; kt < 8; kt++) {
            __syncthreads();
#pragma unroll
            for (int u = 0; u < 16; u++) {
                int i4 = tid + 128 * u;
                int b = i4 >> 5, k4 = (i4 & 31) << 2;
                float4 hv = *(const float4*)(out + ((size_t)b * SS + (t - 1)) * HH
                                             + kt * 128 + k4);
                *(float4*)&Hs[b * 132 + k4] = hv;
            }
            __syncthreads();
#pragma unroll
            for (int g4 = 0; g4 < 4; g4++) {
                const float* wrow = Wh + (size_t)(g4 * HH + j) * HH + kt * 128;
#pragma unroll 4
                for (int k = 0; k < 128; k += 4) {
                    float4 wv = *(const float4*)(wrow + k);
#pragma unroll
                    for (int bz = 0; bz < 4; bz++) {
                        const float* hp = &Hs[(bq + 16 * bz) * 132 + k];
                        facc[g4][bz] = fmaf(wv.x, hp[0],
                                       fmaf(wv.y, hp[1],
                                       fmaf(wv.z, hp[2],
                                       fmaf(wv.w, hp[3], facc[g4][bz]))));
                    }
                }
            }
        }
#pragma unroll
        for (int bz = 0; bz < 4; bz++) {
            const int b = bq + 16 * bz;
            const size_t gb = ((size_t)b * SS + t) * (size_t)GG + j;
            lstm_elem(out, t, wf, b, j,
                      facc[0][bz] + g_gx[gb],
                      facc[1][bz] + g_gx[gb + HH],
                      facc[2][bz] + g_gx[gb + 2 * HH],
                      facc[3][bz] + g_gx[gb + 3 * HH],
                      whp, wlp);
        }
    }
}

// ---------------------------------------------------------------------------
extern "C" void kernel_launch(void* const* d_in, const int* in_sizes, int n_in,
                              void* d_out, int out_size) {
    const float* x  = (const float*)d_in[0];
    const float* Wx = (const float*)d_in[1];
    const float* Wh = (const float*)d_in[2];
    const float* bx = (const float*)d_in[3];
    const float* bh = (const float*)d_in[4];
    float* out = (float*)d_out;

    const long long full = (long long)BB * SS * HH + 2LL * BB * HH;
    const int wf = ((long long)out_size >= full) ? 1 : 0;

    cudaFuncSetAttribute(lstm_step_v7, cudaFuncAttributeMaxDynamicSharedMemorySize,
                         STEP_SMEM);

    split_hl<<<(GG * HH) / 1024, 256>>>(Wh, g_whhi, g_whlo);
    gx_gemm<<<dim3(GG / 64, (BB * SS) / 64), 256>>>(x, Wx, bx, bh);
    for (int t = 0; t < SS; t++) {
        lstm_step_v7<<<128, 128, STEP_SMEM>>>(Wh, out, t, wf);
    }
}

// round 8
// speedup vs baseline: 1.0007x; 1.0007x over previous
#include <cuda_runtime.h>
#include <cuda_bf16.h>
#include <math.h>
#include <stdint.h>

#define BB 64
#define SS 512
#define DD 512
#define HH 1024
#define GG 4096   // 4*HH

// ---------------------------------------------------------------------------
// Device-global scratch. NOTE: bf16 arrays are 256B-aligned — cp.async.cg 16B
// requires 16B-aligned GLOBAL addresses; default bf16 array alignment is 2B.
// ---------------------------------------------------------------------------
__device__ float g_gx[(size_t)BB * SS * GG];
__device__ float g_c[BB * HH];
__device__ __align__(256) __nv_bfloat16 g_whhi[(size_t)GG * HH];
__device__ __align__(256) __nv_bfloat16 g_whlo[(size_t)GG * HH];
__device__ __align__(256) __nv_bfloat16 g_hhi[2][BB * HH];
__device__ __align__(256) __nv_bfloat16 g_hlo[2][BB * HH];
__device__ int g_mma_ok = 1;

// ---------------------------------------------------------------------------
// Portable PTX helpers
// ---------------------------------------------------------------------------
__device__ __forceinline__ uint32_t smem_u32(const void* p) {
    uint32_t a;
    asm("{ .reg .u64 t; cvta.to.shared.u64 t, %1; cvt.u32.u64 %0, t; }" : "=r"(a) : "l"(p));
    return a;
}
__device__ __forceinline__ void cpa16(uint32_t dst, const void* src) {
    asm volatile("cp.async.cg.shared.global [%0], [%1], 16;" :: "r"(dst), "l"(src));
}
#define CP_COMMIT() asm volatile("cp.async.commit_group;" ::: "memory")
#define CP_WAIT(n)  asm volatile("cp.async.wait_group %0;" :: "n"(n) : "memory")

__device__ __forceinline__ uint32_t lds32(uint32_t a) {
    uint32_t v;
    asm volatile("ld.shared.b32 %0, [%1];" : "=r"(v) : "r"(a));
    return v;
}
__device__ __forceinline__ void mma16816(float* d, const uint32_t* a, const uint32_t* b) {
    asm volatile(
        "mma.sync.aligned.m16n8k16.row.col.f32.bf16.bf16.f32 "
        "{%0,%1,%2,%3}, {%4,%5,%6,%7}, {%8,%9}, {%0,%1,%2,%3};"
        : "+f"(d[0]), "+f"(d[1]), "+f"(d[2]), "+f"(d[3])
        : "r"(a[0]), "r"(a[1]), "r"(a[2]), "r"(a[3]), "r"(b[0]), "r"(b[1]));
}

__device__ __forceinline__ float sigf(float x) { return 1.f / (1.f + __expf(-x)); }
__device__ __forceinline__ float tanhfast(float x) { return 1.f - 2.f / (__expf(2.f * x) + 1.f); }

// ---------------------------------------------------------------------------
// Split fp32 -> bf16 hi/lo
// ---------------------------------------------------------------------------
__global__ __launch_bounds__(256) void split_hl(const float* __restrict__ src,
                                                __nv_bfloat16* __restrict__ hi,
                                                __nv_bfloat16* __restrict__ lo) {
    size_t i = (size_t)blockIdx.x * 1024 + (size_t)threadIdx.x * 4;
    float4 w = *(const float4*)(src + i);
    __nv_bfloat16 h0 = __float2bfloat16(w.x), h1 = __float2bfloat16(w.y);
    __nv_bfloat16 h2 = __float2bfloat16(w.z), h3 = __float2bfloat16(w.w);
    *(__nv_bfloat162*)(hi + i)     = __nv_bfloat162(h0, h1);
    *(__nv_bfloat162*)(hi + i + 2) = __nv_bfloat162(h2, h3);
    *(__nv_bfloat162*)(lo + i) =
        __nv_bfloat162(__float2bfloat16(w.x - __bfloat162float(h0)),
                       __float2bfloat16(w.y - __bfloat162float(h1)));
    *(__nv_bfloat162*)(lo + i + 2) =
        __nv_bfloat162(__float2bfloat16(w.z - __bfloat162float(h2)),
                       __float2bfloat16(w.w - __bfloat162float(h3)));
}

// ---------------------------------------------------------------------------
// gx GEMM (fp32, PROVEN in R1)
// ---------------------------------------------------------------------------
__global__ __launch_bounds__(256) void gx_gemm(const float* __restrict__ x,
                                               const float* __restrict__ Wx,
                                               const float* __restrict__ bx,
                                               const float* __restrict__ bh) {
    __shared__ float As[16][64];
    __shared__ float Ws[16][64];
    const int tid = threadIdx.x;
    const int tx = tid & 15, ty = tid >> 4;
    const int m0 = blockIdx.y * 64, n0 = blockIdx.x * 64;
    const int lrow = tid >> 2, lk = (tid & 3) << 2;

    float acc[4][4];
#pragma unroll
    for (int i = 0; i < 4; i++)
#pragma unroll
        for (int j = 0; j < 4; j++) acc[i][j] = 0.f;

    const float* aptr = x + (size_t)(m0 + lrow) * DD + lk;
    const float* wptr = Wx + (size_t)(n0 + lrow) * DD + lk;

    for (int kt = 0; kt < DD; kt += 16) {
        float4 av = *(const float4*)(aptr + kt);
        float4 wv = *(const float4*)(wptr + kt);
        __syncthreads();
        As[lk + 0][lrow] = av.x; As[lk + 1][lrow] = av.y;
        As[lk + 2][lrow] = av.z; As[lk + 3][lrow] = av.w;
        Ws[lk + 0][lrow] = wv.x; Ws[lk + 1][lrow] = wv.y;
        Ws[lk + 2][lrow] = wv.z; Ws[lk + 3][lrow] = wv.w;
        __syncthreads();
#pragma unroll
        for (int kk = 0; kk < 16; kk++) {
            float4 a4 = *(const float4*)&As[kk][ty * 4];
            float4 b4 = *(const float4*)&Ws[kk][tx * 4];
            float a[4] = {a4.x, a4.y, a4.z, a4.w};
            float b[4] = {b4.x, b4.y, b4.z, b4.w};
#pragma unroll
            for (int i = 0; i < 4; i++)
#pragma unroll
                for (int j = 0; j < 4; j++) acc[i][j] = fmaf(a[i], b[j], acc[i][j]);
        }
    }
    const int nb = n0 + tx * 4;
    float4 bias;
    bias.x = bx[nb + 0] + bh[nb + 0];
    bias.y = bx[nb + 1] + bh[nb + 1];
    bias.z = bx[nb + 2] + bh[nb + 2];
    bias.w = bx[nb + 3] + bh[nb + 3];
#pragma unroll
    for (int i = 0; i < 4; i++) {
        const size_t m = (size_t)(m0 + ty * 4 + i);
        float4 v;
        v.x = acc[i][0] + bias.x; v.y = acc[i][1] + bias.y;
        v.z = acc[i][2] + bias.z; v.w = acc[i][3] + bias.w;
        *(float4*)&g_gx[m * GG + nb] = v;
    }
}

// ===========================================================================
// Step kernel: dual path with END-TO-END verification at t=1.
// smem buffer (27648 B each, x2), pitch 144 B:
//   Ah[32][72] @0, Al @4608, Bh[64][72] @9216, Bl @18432
// ===========================================================================
#define STEP_BUF 27648
#define STEP_SMEM (2 * STEP_BUF)

__device__ __forceinline__ void step_load(uint32_t sb, int s, int tid, int j0, int kc,
                                          const __nv_bfloat16* __restrict__ rh,
                                          const __nv_bfloat16* __restrict__ rl) {
    uint32_t ab = sb + s * STEP_BUF;
#pragma unroll
    for (int i = 0; i < 2; i++) {
        int idx = tid + 128 * i, row = idx >> 3, k8 = idx & 7;
        size_t go = ((size_t)((row >> 3) * HH + j0 + (row & 7))) * HH
                  + (size_t)kc * 64 + (size_t)k8 * 8;
        uint32_t d = ab + row * 144 + k8 * 16;
        cpa16(d, g_whhi + go);
        cpa16(d + 4608, g_whlo + go);
    }
#pragma unroll
    for (int i = 0; i < 4; i++) {
        int idx = tid + 128 * i, b = idx >> 3, k8 = idx & 7;
        size_t go = (size_t)b * HH + (size_t)kc * 64 + (size_t)k8 * 8;
        uint32_t d = ab + 9216 + b * 144 + k8 * 16;
        cpa16(d, rh + go);
        cpa16(d + 9216, rl + go);
    }
    CP_COMMIT();
}

// A frag (m16k16): a0=(g,2t..), a1=(g+8,..), a2=(g,2t+8..), a3=(g+8,2t+8..)
__device__ __forceinline__ void loadA(uint32_t base, int r0, int g, uint32_t ka,
                                      uint32_t* a) {
    a[0] = lds32(base + (r0 + g) * 144 + ka);
    a[1] = lds32(base + (r0 + g + 8) * 144 + ka);
    a[2] = lds32(base + (r0 + g) * 144 + ka + 16);
    a[3] = lds32(base + (r0 + g + 8) * 144 + ka + 16);
}
// B frag (k16n8): b0=(k=2t.., n=g), b1=(k=2t+8.., n=g); smem row = n
__device__ __forceinline__ void loadB(uint32_t base, int nb, int g, uint32_t ka,
                                      uint32_t* b) {
    b[0] = lds32(base + (nb + g) * 144 + ka);
    b[1] = lds32(base + (nb + g) * 144 + ka + 16);
}

__device__ __forceinline__ void step_compute(uint32_t sb, int s, int lane, int wid,
                                             float (&acc)[2][2][4]) {
    uint32_t ab = sb + s * STEP_BUF;
    const int g = lane >> 2, tig = lane & 3;
    const uint32_t aB = ab + 9216;
#pragma unroll
    for (int kk = 0; kk < 4; kk++) {
        const uint32_t ka = (uint32_t)((kk * 16 + 2 * tig) * 2);
        uint32_t ah0[4], ah1[4], al0[4], al1[4], bh[2][2], bl[2][2];
        loadA(ab, 0, g, ka, ah0);
        loadA(ab, 16, g, ka, ah1);
        loadA(ab + 4608, 0, g, ka, al0);
        loadA(ab + 4608, 16, g, ka, al1);
        loadB(aB, wid * 16, g, ka, bh[0]);
        loadB(aB, wid * 16 + 8, g, ka, bh[1]);
        loadB(aB + 9216, wid * 16, g, ka, bl[0]);
        loadB(aB + 9216, wid * 16 + 8, g, ka, bl[1]);
        mma16816(acc[0][0], ah0, bh[0]);  mma16816(acc[0][1], ah0, bh[1]);
        mma16816(acc[1][0], ah1, bh[0]);  mma16816(acc[1][1], ah1, bh[1]);
        mma16816(acc[0][0], ah0, bl[0]);  mma16816(acc[0][1], ah0, bl[1]);
        mma16816(acc[1][0], ah1, bl[0]);  mma16816(acc[1][1], ah1, bl[1]);
        mma16816(acc[0][0], al0, bh[0]);  mma16816(acc[0][1], al0, bh[1]);
        mma16816(acc[1][0], al1, bh[0]);  mma16816(acc[1][1], al1, bh[1]);
    }
}

__device__ __forceinline__ void lstm_elem(float* out, int t, int wf, int b, int j,
                                          float iv, float fv, float gv, float ov,
                                          __nv_bfloat16* whp, __nv_bfloat16* wlp) {
    iv = sigf(iv); fv = sigf(fv); gv = tanhfast(gv); ov = sigf(ov);
    const float cp = g_c[b * HH + j];
    const float cn = fmaf(fv, cp, iv * gv);
    const float hn = ov * tanhfast(cn);
    g_c[b * HH + j] = cn;
    out[((size_t)b * SS + t) * HH + j] = hn;
    __nv_bfloat16 hb = __float2bfloat16(hn);
    whp[b * HH + j] = hb;
    wlp[b * HH + j] = __float2bfloat16(hn - __bfloat162float(hb));
    if (wf && t == SS - 1) {
        out[(size_t)BB * SS * HH + (size_t)b * HH + j] = hn;
        out[(size_t)BB * SS * HH + (size_t)BB * HH + (size_t)b * HH + j] = cn;
    }
}

__global__ __launch_bounds__(128) void lstm_step_v8(const float* __restrict__ Wh,
                                                    float* __restrict__ out,
                                                    int t, int wf) {
    const int tid = threadIdx.x;
    const int j0 = blockIdx.x * 8;

    __nv_bfloat16* whp = g_hhi[t & 1];
    __nv_bfloat16* wlp = g_hlo[t & 1];

    if (t == 0) {
        for (int idx = tid; idx < 512; idx += 128) {
            int b = idx >> 3, jl = idx & 7, j = j0 + jl;
            size_t gb = (size_t)b * SS * GG + j;
            float iv = sigf(g_gx[gb]);
            float gv = tanhfast(g_gx[gb + 2 * HH]);
            float ov = sigf(g_gx[gb + 3 * HH]);
            float cn = iv * gv;
            float hn = ov * tanhfast(cn);
            g_c[b * HH + j] = cn;
            out[((size_t)b * SS) * HH + j] = hn;
            __nv_bfloat16 hb = __float2bfloat16(hn);
            whp[b * HH + j] = hb;
            wlp[b * HH + j] = __float2bfloat16(hn - __bfloat162float(hb));
        }
        return;
    }

    extern __shared__ __align__(128) char sm[];
    __shared__ int s_bad;
    const uint32_t sb = smem_u32(sm);
    const int wid = tid >> 5, lane = tid & 31;
    const int g = lane >> 2, q = lane & 3;

    int use_mma = (t == 1) ? 1 : *(volatile int*)&g_mma_ok;

    float acc[2][2][4];
#pragma unroll
    for (int r = 0; r < 2; r++)
#pragma unroll
        for (int c = 0; c < 2; c++)
#pragma unroll
            for (int e = 0; e < 4; e++) acc[r][c][e] = 0.f;

    if (use_mma) {
        const __nv_bfloat16* rh = g_hhi[(t - 1) & 1];
        const __nv_bfloat16* rl = g_hlo[(t - 1) & 1];

        step_load(sb, 0, tid, j0, 0, rh, rl);
#pragma unroll 1
        for (int kc = 0; kc < 16; kc++) {
            const int s = kc & 1;
            if (kc < 15) step_load(sb, s ^ 1, tid, j0, kc + 1, rh, rl);
            if (kc < 15) { CP_WAIT(1); } else { CP_WAIT(0); }
            __syncthreads();
            step_compute(sb, s, lane, wid, acc);
            __syncthreads();
        }

        if (t == 1) {
            // END-TO-END verify: recompute all 16 acc elements in fp32 from
            // Wh (fp32) and out[t=0] (fp32).
            if (tid == 0) s_bad = 0;
            __syncthreads();
            const int j = j0 + g;
            int bc[4];
#pragma unroll
            for (int ci = 0; ci < 4; ci++)
                bc[ci] = wid * 16 + (ci >> 1) * 8 + 2 * q + (ci & 1);
            float ref[4][4];
#pragma unroll
            for (int ga = 0; ga < 4; ga++)
#pragma unroll
                for (int ci = 0; ci < 4; ci++) ref[ga][ci] = 0.f;
            const float* w0 = Wh + (size_t)(0 * HH + j) * HH;
            const float* w1 = Wh + (size_t)(1 * HH + j) * HH;
            const float* w2 = Wh + (size_t)(2 * HH + j) * HH;
            const float* w3 = Wh + (size_t)(3 * HH + j) * HH;
#pragma unroll 4
            for (int k = 0; k < HH; k++) {
                float wv[4] = {w0[k], w1[k], w2[k], w3[k]};
                float hv[4];
#pragma unroll
                for (int ci = 0; ci < 4; ci++)
                    hv[ci] = out[((size_t)bc[ci] * SS + 0) * HH + k];
#pragma unroll
                for (int ga = 0; ga < 4; ga++)
#pragma unroll
                    for (int ci = 0; ci < 4; ci++)
                        ref[ga][ci] = fmaf(wv[ga], hv[ci], ref[ga][ci]);
            }
            bool ok = true;
#pragma unroll
            for (int ga = 0; ga < 4; ga++)
#pragma unroll
                for (int ci = 0; ci < 4; ci++) {
                    float av = acc[ga >> 1][ci >> 1][((ga & 1) << 1) | (ci & 1)];
                    float rv = ref[ga][ci];
                    ok &= fabsf(av - rv) <= (2e-4f + 2e-4f * fabsf(rv));
                }
            if (!ok) s_bad = 1;
            __syncthreads();
            if (s_bad) {
                if (tid == 0) g_mma_ok = 0;
                use_mma = 0;
            }
        }
    }

    if (use_mma) {
        const int j = j0 + g;
        const int n0 = wid * 16;
#pragma unroll
        for (int c = 0; c < 2; c++)
#pragma unroll
            for (int e = 0; e < 2; e++) {
                const int b = n0 + c * 8 + 2 * q + e;
                const size_t gb = ((size_t)b * SS + t) * (size_t)GG + j;
                lstm_elem(out, t, wf, b, j,
                          acc[0][c][e]     + g_gx[gb],
                          acc[0][c][2 + e] + g_gx[gb + HH],
                          acc[1][c][e]     + g_gx[gb + 2 * HH],
                          acc[1][c][2 + e] + g_gx[gb + 3 * HH],
                          whp, wlp);
            }
    } else {
        // fp32 FFMA fallback (independent of staging/mma machinery).
        __syncthreads();
        float* Hs = (float*)sm;                 // [64][132] floats
        const int bq = tid >> 3, jl = tid & 7;
        const int j = j0 + jl;
        float facc[4][4];
#pragma unroll
        for (int a = 0; a < 4; a++)
#pragma unroll
            for (int bz = 0; bz < 4; bz++) facc[a][bz] = 0.f;

#pragma unroll 1
        for (int kt = 0; kt < 8; kt++) {
            __syncthreads();
#pragma unroll
            for (int u = 0; u < 16; u++) {
                int i4 = tid + 128 * u;
                int b = i4 >> 5, k4 = (i4 & 31) << 2;
                float4 hv = *(const float4*)(out + ((size_t)b * SS + (t - 1)) * HH
                                             + kt * 128 + k4);
                *(float4*)&Hs[b * 132 + k4] = hv;
            }
            __syncthreads();
#pragma unroll
            for (int g4 = 0; g4 < 4; g4++) {
                const float* wrow = Wh + (size_t)(g4 * HH + j) * HH + kt * 128;
#pragma unroll 4
                for (int k = 0; k < 128; k += 4) {
                    float4 wv = *(const float4*)(wrow + k);
#pragma unroll
                    for (int bz = 0; bz < 4; bz++) {
                        const float* hp = &Hs[(bq + 16 * bz) * 132 + k];
                        facc[g4][bz] = fmaf(wv.x, hp[0],
                                       fmaf(wv.y, hp[1],
                                       fmaf(wv.z, hp[2],
                                       fmaf(wv.w, hp[3], facc[g4][bz]))));
                    }
                }
            }
        }
#pragma unroll
        for (int bz = 0; bz < 4; bz++) {
            const int b = bq + 16 * bz;
            const size_t gb = ((size_t)b * SS + t) * (size_t)GG + j;
            lstm_elem(out, t, wf, b, j,
                      facc[0][bz] + g_gx[gb],
                      facc[1][bz] + g_gx[gb + HH],
                      facc[2][bz] + g_gx[gb + 2 * HH],
                      facc[3][bz] + g_gx[gb + 3 * HH],
                      whp, wlp);
        }
    }
}

// ---------------------------------------------------------------------------
extern "C" void kernel_launch(void* const* d_in, const int* in_sizes, int n_in,
                              void* d_out, int out_size) {
    const float* x  = (const float*)d_in[0];
    const float* Wx = (const float*)d_in[1];
    const float* Wh = (const float*)d_in[2];
    const float* bx = (const float*)d_in[3];
    const float* bh = (const float*)d_in[4];
    float* out = (float*)d_out;

    const long long full = (long long)BB * SS * HH + 2LL * BB * HH;
    const int wf = ((long long)out_size >= full) ? 1 : 0;

    cudaFuncSetAttribute(lstm_step_v8, cudaFuncAttributeMaxDynamicSharedMemorySize,
                         STEP_SMEM);

    split_hl<<<(GG * HH) / 1024, 256>>>(Wh, g_whhi, g_whlo);
    gx_gemm<<<dim3(GG / 64, (BB * SS) / 64), 256>>>(x, Wx, bx, bh);
    for (int t = 0; t < SS; t++) {
        lstm_step_v8<<<128, 128, STEP_SMEM>>>(Wh, out, t, wf);
    }
}

// round 9
// speedup vs baseline: 1.4298x; 1.4288x over previous
#include <cuda_runtime.h>
#include <cuda_bf16.h>
#include <math.h>
#include <stdint.h>

#define BB 64
#define SS 512
#define DD 512
#define HH 1024
#define GG 4096   // 4*HH

// ---------------------------------------------------------------------------
// Device-global scratch (no allocations allowed anywhere).
// ---------------------------------------------------------------------------
__device__ float g_gx[(size_t)BB * SS * GG];
__device__ float g_c[BB * HH];
__device__ __align__(256) __nv_bfloat16 g_whhi[(size_t)GG * HH];
__device__ __align__(256) __nv_bfloat16 g_whlo[(size_t)GG * HH];
__device__ __align__(256) __nv_bfloat16 g_hhi[2][BB * HH];
__device__ __align__(256) __nv_bfloat16 g_hlo[2][BB * HH];
__device__ int g_mma_ok = 1;

// ---------------------------------------------------------------------------
// Portable PTX helpers (NO cp.async anywhere — staging is LDG->regs->STS)
// ---------------------------------------------------------------------------
__device__ __forceinline__ uint32_t smem_u32(const void* p) {
    uint32_t a;
    asm("{ .reg .u64 t; cvta.to.shared.u64 t, %1; cvt.u32.u64 %0, t; }" : "=r"(a) : "l"(p));
    return a;
}
__device__ __forceinline__ uint32_t lds32(uint32_t a) {
    uint32_t v;
    asm volatile("ld.shared.b32 %0, [%1];" : "=r"(v) : "r"(a));
    return v;
}
__device__ __forceinline__ void mma16816(float* d, const uint32_t* a, const uint32_t* b) {
    asm volatile(
        "mma.sync.aligned.m16n8k16.row.col.f32.bf16.bf16.f32 "
        "{%0,%1,%2,%3}, {%4,%5,%6,%7}, {%8,%9}, {%0,%1,%2,%3};"
        : "+f"(d[0]), "+f"(d[1]), "+f"(d[2]), "+f"(d[3])
        : "r"(a[0]), "r"(a[1]), "r"(a[2]), "r"(a[3]), "r"(b[0]), "r"(b[1]));
}

__device__ __forceinline__ float sigf(float x) { return 1.f / (1.f + __expf(-x)); }
__device__ __forceinline__ float tanhfast(float x) { return 1.f - 2.f / (__expf(2.f * x) + 1.f); }

// ---------------------------------------------------------------------------
// Split fp32 -> bf16 hi/lo
// ---------------------------------------------------------------------------
__global__ __launch_bounds__(256) void split_hl(const float* __restrict__ src,
                                                __nv_bfloat16* __restrict__ hi,
                                                __nv_bfloat16* __restrict__ lo) {
    size_t i = (size_t)blockIdx.x * 1024 + (size_t)threadIdx.x * 4;
    float4 w = *(const float4*)(src + i);
    __nv_bfloat16 h0 = __float2bfloat16(w.x), h1 = __float2bfloat16(w.y);
    __nv_bfloat16 h2 = __float2bfloat16(w.z), h3 = __float2bfloat16(w.w);
    *(__nv_bfloat162*)(hi + i)     = __nv_bfloat162(h0, h1);
    *(__nv_bfloat162*)(hi + i + 2) = __nv_bfloat162(h2, h3);
    *(__nv_bfloat162*)(lo + i) =
        __nv_bfloat162(__float2bfloat16(w.x - __bfloat162float(h0)),
                       __float2bfloat16(w.y - __bfloat162float(h1)));
    *(__nv_bfloat162*)(lo + i + 2) =
        __nv_bfloat162(__float2bfloat16(w.z - __bfloat162float(h2)),
                       __float2bfloat16(w.w - __bfloat162float(h3)));
}

// ---------------------------------------------------------------------------
// gx GEMM (fp32, PROVEN in R1)
// ---------------------------------------------------------------------------
__global__ __launch_bounds__(256) void gx_gemm(const float* __restrict__ x,
                                               const float* __restrict__ Wx,
                                               const float* __restrict__ bx,
                                               const float* __restrict__ bh) {
    __shared__ float As[16][64];
    __shared__ float Ws[16][64];
    const int tid = threadIdx.x;
    const int tx = tid & 15, ty = tid >> 4;
    const int m0 = blockIdx.y * 64, n0 = blockIdx.x * 64;
    const int lrow = tid >> 2, lk = (tid & 3) << 2;

    float acc[4][4];
#pragma unroll
    for (int i = 0; i < 4; i++)
#pragma unroll
        for (int j = 0; j < 4; j++) acc[i][j] = 0.f;

    const float* aptr = x + (size_t)(m0 + lrow) * DD + lk;
    const float* wptr = Wx + (size_t)(n0 + lrow) * DD + lk;

    for (int kt = 0; kt < DD; kt += 16) {
        float4 av = *(const float4*)(aptr + kt);
        float4 wv = *(const float4*)(wptr + kt);
        __syncthreads();
        As[lk + 0][lrow] = av.x; As[lk + 1][lrow] = av.y;
        As[lk + 2][lrow] = av.z; As[lk + 3][lrow] = av.w;
        Ws[lk + 0][lrow] = wv.x; Ws[lk + 1][lrow] = wv.y;
        Ws[lk + 2][lrow] = wv.z; Ws[lk + 3][lrow] = wv.w;
        __syncthreads();
#pragma unroll
        for (int kk = 0; kk < 16; kk++) {
            float4 a4 = *(const float4*)&As[kk][ty * 4];
            float4 b4 = *(const float4*)&Ws[kk][tx * 4];
            float a[4] = {a4.x, a4.y, a4.z, a4.w};
            float b[4] = {b4.x, b4.y, b4.z, b4.w};
#pragma unroll
            for (int i = 0; i < 4; i++)
#pragma unroll
                for (int j = 0; j < 4; j++) acc[i][j] = fmaf(a[i], b[j], acc[i][j]);
        }
    }
    const int nb = n0 + tx * 4;
    float4 bias;
    bias.x = bx[nb + 0] + bh[nb + 0];
    bias.y = bx[nb + 1] + bh[nb + 1];
    bias.z = bx[nb + 2] + bh[nb + 2];
    bias.w = bx[nb + 3] + bh[nb + 3];
#pragma unroll
    for (int i = 0; i < 4; i++) {
        const size_t m = (size_t)(m0 + ty * 4 + i);
        float4 v;
        v.x = acc[i][0] + bias.x; v.y = acc[i][1] + bias.y;
        v.z = acc[i][2] + bias.z; v.w = acc[i][3] + bias.w;
        *(float4*)&g_gx[m * GG + nb] = v;
    }
}

// ===========================================================================
// Step kernel: staging via LDG(uint4)->registers->STS(uint4); smem double-buf.
// All smem-consumer machinery (lds32 fragments + mma + D map) is the
// hardware-verified R6 path. e2e verify at t=1 + fp32 fallback kept.
// smem buffer (27648 B each, x2), pitch 144 B:
//   Ah[32][72] @0, Al @4608, Bh[64][72] @9216, Bl @18432
// ===========================================================================
#define STEP_BUF 27648
#define STEP_SMEM (2 * STEP_BUF)

struct StFrag {
    uint4 ah[2], al[2], bh[4], bl[4];
};

__device__ __forceinline__ void ldg_chunk(StFrag& f, int tid, int j0, int kc,
                                          const __nv_bfloat16* __restrict__ rh,
                                          const __nv_bfloat16* __restrict__ rl) {
#pragma unroll
    for (int i = 0; i < 2; i++) {
        int idx = tid + 128 * i, row = idx >> 3, k8 = idx & 7;
        size_t go = ((size_t)((row >> 3) * HH + j0 + (row & 7))) * HH
                  + (size_t)kc * 64 + (size_t)k8 * 8;
        f.ah[i] = *(const uint4*)(g_whhi + go);
        f.al[i] = *(const uint4*)(g_whlo + go);
    }
#pragma unroll
    for (int i = 0; i < 4; i++) {
        int idx = tid + 128 * i, b = idx >> 3, k8 = idx & 7;
        size_t go = (size_t)b * HH + (size_t)kc * 64 + (size_t)k8 * 8;
        f.bh[i] = *(const uint4*)(rh + go);
        f.bl[i] = *(const uint4*)(rl + go);
    }
}

__device__ __forceinline__ void sts_chunk(const StFrag& f, char* ab, int tid) {
#pragma unroll
    for (int i = 0; i < 2; i++) {
        int idx = tid + 128 * i, row = idx >> 3, k8 = idx & 7;
        char* d = ab + row * 144 + k8 * 16;
        *(uint4*)(d)        = f.ah[i];
        *(uint4*)(d + 4608) = f.al[i];
    }
#pragma unroll
    for (int i = 0; i < 4; i++) {
        int idx = tid + 128 * i, b = idx >> 3, k8 = idx & 7;
        char* d = ab + 9216 + b * 144 + k8 * 16;
        *(uint4*)(d)        = f.bh[i];
        *(uint4*)(d + 9216) = f.bl[i];
    }
}

// A frag (m16k16): a0=(g,2t..), a1=(g+8,..), a2=(g,2t+8..), a3=(g+8,2t+8..)
__device__ __forceinline__ void loadA(uint32_t base, int r0, int g, uint32_t ka,
                                      uint32_t* a) {
    a[0] = lds32(base + (r0 + g) * 144 + ka);
    a[1] = lds32(base + (r0 + g + 8) * 144 + ka);
    a[2] = lds32(base + (r0 + g) * 144 + ka + 16);
    a[3] = lds32(base + (r0 + g + 8) * 144 + ka + 16);
}
// B frag (k16n8): b0=(k=2t.., n=g), b1=(k=2t+8.., n=g); smem row = n
__device__ __forceinline__ void loadB(uint32_t base, int nb, int g, uint32_t ka,
                                      uint32_t* b) {
    b[0] = lds32(base + (nb + g) * 144 + ka);
    b[1] = lds32(base + (nb + g) * 144 + ka + 16);
}

__device__ __forceinline__ void step_compute(uint32_t sb, int s, int lane, int wid,
                                             float (&acc)[2][2][4]) {
    uint32_t ab = sb + s * STEP_BUF;
    const int g = lane >> 2, tig = lane & 3;
    const uint32_t aB = ab + 9216;
#pragma unroll
    for (int kk = 0; kk < 4; kk++) {
        const uint32_t ka = (uint32_t)((kk * 16 + 2 * tig) * 2);
        uint32_t ah0[4], ah1[4], al0[4], al1[4], bh[2][2], bl[2][2];
        loadA(ab, 0, g, ka, ah0);
        loadA(ab, 16, g, ka, ah1);
        loadA(ab + 4608, 0, g, ka, al0);
        loadA(ab + 4608, 16, g, ka, al1);
        loadB(aB, wid * 16, g, ka, bh[0]);
        loadB(aB, wid * 16 + 8, g, ka, bh[1]);
        loadB(aB + 9216, wid * 16, g, ka, bl[0]);
        loadB(aB + 9216, wid * 16 + 8, g, ka, bl[1]);
        mma16816(acc[0][0], ah0, bh[0]);  mma16816(acc[0][1], ah0, bh[1]);
        mma16816(acc[1][0], ah1, bh[0]);  mma16816(acc[1][1], ah1, bh[1]);
        mma16816(acc[0][0], ah0, bl[0]);  mma16816(acc[0][1], ah0, bl[1]);
        mma16816(acc[1][0], ah1, bl[0]);  mma16816(acc[1][1], ah1, bl[1]);
        mma16816(acc[0][0], al0, bh[0]);  mma16816(acc[0][1], al0, bh[1]);
        mma16816(acc[1][0], al1, bh[0]);  mma16816(acc[1][1], al1, bh[1]);
    }
}

__device__ __forceinline__ void lstm_elem(float* out, int t, int wf, int b, int j,
                                          float iv, float fv, float gv, float ov,
                                          __nv_bfloat16* whp, __nv_bfloat16* wlp) {
    iv = sigf(iv); fv = sigf(fv); gv = tanhfast(gv); ov = sigf(ov);
    const float cp = g_c[b * HH + j];
    const float cn = fmaf(fv, cp, iv * gv);
    const float hn = ov * tanhfast(cn);
    g_c[b * HH + j] = cn;
    out[((size_t)b * SS + t) * HH + j] = hn;
    __nv_bfloat16 hb = __float2bfloat16(hn);
    whp[b * HH + j] = hb;
    wlp[b * HH + j] = __float2bfloat16(hn - __bfloat162float(hb));
    if (wf && t == SS - 1) {
        out[(size_t)BB * SS * HH + (size_t)b * HH + j] = hn;
        out[(size_t)BB * SS * HH + (size_t)BB * HH + (size_t)b * HH + j] = cn;
    }
}

__global__ __launch_bounds__(128) void lstm_step_v9(const float* __restrict__ Wh,
                                                    float* __restrict__ out,
                                                    int t, int wf) {
    const int tid = threadIdx.x;
    const int j0 = blockIdx.x * 8;

    __nv_bfloat16* whp = g_hhi[t & 1];
    __nv_bfloat16* wlp = g_hlo[t & 1];

    if (t == 0) {
        for (int idx = tid; idx < 512; idx += 128) {
            int b = idx >> 3, jl = idx & 7, j = j0 + jl;
            size_t gb = (size_t)b * SS * GG + j;
            float iv = sigf(g_gx[gb]);
            float gv = tanhfast(g_gx[gb + 2 * HH]);
            float ov = sigf(g_gx[gb + 3 * HH]);
            float cn = iv * gv;
            float hn = ov * tanhfast(cn);
            g_c[b * HH + j] = cn;
            out[((size_t)b * SS) * HH + j] = hn;
            __nv_bfloat16 hb = __float2bfloat16(hn);
            whp[b * HH + j] = hb;
            wlp[b * HH + j] = __float2bfloat16(hn - __bfloat162float(hb));
        }
        return;
    }

    extern __shared__ __align__(128) char sm[];
    __shared__ int s_bad;
    const uint32_t sb = smem_u32(sm);
    const int wid = tid >> 5, lane = tid & 31;
    const int g = lane >> 2, q = lane & 3;

    int use_mma = (t == 1) ? 1 : *(volatile int*)&g_mma_ok;

    float acc[2][2][4];
#pragma unroll
    for (int r = 0; r < 2; r++)
#pragma unroll
        for (int c = 0; c < 2; c++)
#pragma unroll
            for (int e = 0; e < 4; e++) acc[r][c][e] = 0.f;

    if (use_mma) {
        const __nv_bfloat16* rh = g_hhi[(t - 1) & 1];
        const __nv_bfloat16* rl = g_hlo[(t - 1) & 1];

        StFrag fr;
        ldg_chunk(fr, tid, j0, 0, rh, rl);
        sts_chunk(fr, sm, tid);
#pragma unroll 1
        for (int kc = 0; kc < 16; kc++) {
            const int s = kc & 1;
            __syncthreads();                 // buf s stores visible CTA-wide
            if (kc < 15) ldg_chunk(fr, tid, j0, kc + 1, rh, rl);  // prefetch
            step_compute(sb, s, lane, wid, acc);
            if (kc < 15) sts_chunk(fr, sm + (s ^ 1) * STEP_BUF, tid);
        }

        if (t == 1) {
            // END-TO-END verify vs fp32 truth from Wh and out[t=0].
            if (tid == 0) s_bad = 0;
            __syncthreads();
            const int j = j0 + g;
            int bc[4];
#pragma unroll
            for (int ci = 0; ci < 4; ci++)
                bc[ci] = wid * 16 + (ci >> 1) * 8 + 2 * q + (ci & 1);
            float ref[4][4];
#pragma unroll
            for (int ga = 0; ga < 4; ga++)
#pragma unroll
                for (int ci = 0; ci < 4; ci++) ref[ga][ci] = 0.f;
            const float* w0 = Wh + (size_t)(0 * HH + j) * HH;
            const float* w1 = Wh + (size_t)(1 * HH + j) * HH;
            const float* w2 = Wh + (size_t)(2 * HH + j) * HH;
            const float* w3 = Wh + (size_t)(3 * HH + j) * HH;
#pragma unroll 4
            for (int k = 0; k < HH; k++) {
                float wv[4] = {w0[k], w1[k], w2[k], w3[k]};
                float hv[4];
#pragma unroll
                for (int ci = 0; ci < 4; ci++)
                    hv[ci] = out[((size_t)bc[ci] * SS + 0) * HH + k];
#pragma unroll
                for (int ga = 0; ga < 4; ga++)
#pragma unroll
                    for (int ci = 0; ci < 4; ci++)
                        ref[ga][ci] = fmaf(wv[ga], hv[ci], ref[ga][ci]);
            }
            bool ok = true;
#pragma unroll
            for (int ga = 0; ga < 4; ga++)
#pragma unroll
                for (int ci = 0; ci < 4; ci++) {
                    float av = acc[ga >> 1][ci >> 1][((ga & 1) << 1) | (ci & 1)];
                    float rv = ref[ga][ci];
                    ok &= fabsf(av - rv) <= (1e-3f + 1e-3f * fabsf(rv));
                }
            if (!ok) s_bad = 1;
            __syncthreads();
            if (s_bad) {
                if (tid == 0) g_mma_ok = 0;
                use_mma = 0;
            }
        }
    }

    if (use_mma) {
        const int j = j0 + g;
        const int n0 = wid * 16;
#pragma unroll
        for (int c = 0; c < 2; c++)
#pragma unroll
            for (int e = 0; e < 2; e++) {
                const int b = n0 + c * 8 + 2 * q + e;
                const size_t gb = ((size_t)b * SS + t) * (size_t)GG + j;
                lstm_elem(out, t, wf, b, j,
                          acc[0][c][e]     + g_gx[gb],
                          acc[0][c][2 + e] + g_gx[gb + HH],
                          acc[1][c][e]     + g_gx[gb + 2 * HH],
                          acc[1][c][2 + e] + g_gx[gb + 3 * HH],
                          whp, wlp);
            }
    } else {
        // fp32 FFMA fallback (independent of staging/mma machinery).
        __syncthreads();
        float* Hs = (float*)sm;                 // [64][132] floats
        const int bq = tid >> 3, jl = tid & 7;
        const int j = j0 + jl;
        float facc[4][4];
#pragma unroll
        for (int a = 0; a < 4; a++)
#pragma unroll
            for (int bz = 0; bz < 4; bz++) facc[a][bz] = 0.f;

#pragma unroll 1
        for (int kt = 0; kt < 8; kt++) {
            __syncthreads();
#pragma unroll
            for (int u = 0; u < 16; u++) {
                int i4 = tid + 128 * u;
                int b = i4 >> 5, k4 = (i4 & 31) << 2;
                float4 hv = *(const float4*)(out + ((size_t)b * SS + (t - 1)) * HH
                                             + kt * 128 + k4);
                *(float4*)&Hs[b * 132 + k4] = hv;
            }
            __syncthreads();
#pragma unroll
            for (int g4 = 0; g4 < 4; g4++) {
                const float* wrow = Wh + (size_t)(g4 * HH + j) * HH + kt * 128;
#pragma unroll 4
                for (int k = 0; k < 128; k += 4) {
                    float4 wv = *(const float4*)(wrow + k);
#pragma unroll
                    for (int bz = 0; bz < 4; bz++) {
                        const float* hp = &Hs[(bq + 16 * bz) * 132 + k];
                        facc[g4][bz] = fmaf(wv.x, hp[0],
                                       fmaf(wv.y, hp[1],
                                       fmaf(wv.z, hp[2],
                                       fmaf(wv.w, hp[3], facc[g4][bz]))));
                    }
                }
            }
        }
#pragma unroll
        for (int bz = 0; bz < 4; bz++) {
            const int b = bq + 16 * bz;
            const size_t gb = ((size_t)b * SS + t) * (size_t)GG + j;
            lstm_elem(out, t, wf, b, j,
                      facc[0][bz] + g_gx[gb],
                      facc[1][bz] + g_gx[gb + HH],
                      facc[2][bz] + g_gx[gb + 2 * HH],
                      facc[3][bz] + g_gx[gb + 3 * HH],
                      whp, wlp);
        }
    }
}

// ---------------------------------------------------------------------------
extern "C" void kernel_launch(void* const* d_in, const int* in_sizes, int n_in,
                              void* d_out, int out_size) {
    const float* x  = (const float*)d_in[0];
    const float* Wx = (const float*)d_in[1];
    const float* Wh = (const float*)d_in[2];
    const float* bx = (const float*)d_in[3];
    const float* bh = (const float*)d_in[4];
    float* out = (float*)d_out;

    const long long full = (long long)BB * SS * HH + 2LL * BB * HH;
    const int wf = ((long long)out_size >= full) ? 1 : 0;

    cudaFuncSetAttribute(lstm_step_v9, cudaFuncAttributeMaxDynamicSharedMemorySize,
                         STEP_SMEM);

    split_hl<<<(GG * HH) / 1024, 256>>>(Wh, g_whhi, g_whlo);
    gx_gemm<<<dim3(GG / 64, (BB * SS) / 64), 256>>>(x, Wx, bx, bh);
    for (int t = 0; t < SS; t++) {
        lstm_step_v9<<<128, 128, STEP_SMEM>>>(Wh, out, t, wf);
    }
}

// round 10
// speedup vs baseline: 7.5098x; 5.2522x over previous
#include <cuda_runtime.h>
#include <cuda_bf16.h>
#include <math.h>
#include <stdint.h>

#define BB 64
#define SS 512
#define DD 512
#define HH 1024
#define GG 4096   // 4*HH

// ---------------------------------------------------------------------------
// Device-global scratch (no allocations allowed anywhere).
// NEVER pass these as host-side kernel arguments — host sees shadow symbols!
// ---------------------------------------------------------------------------
__device__ float g_gx[(size_t)BB * SS * GG];
__device__ float g_c[BB * HH];
__device__ __align__(256) __nv_bfloat16 g_whhi[(size_t)GG * HH];
__device__ __align__(256) __nv_bfloat16 g_whlo[(size_t)GG * HH];
__device__ __align__(256) __nv_bfloat16 g_hhi[2][BB * HH];
__device__ __align__(256) __nv_bfloat16 g_hlo[2][BB * HH];
__device__ int g_mma_ok = 1;

// ---------------------------------------------------------------------------
// Portable PTX helpers
// ---------------------------------------------------------------------------
__device__ __forceinline__ uint32_t smem_u32(const void* p) {
    uint32_t a;
    asm("{ .reg .u64 t; cvta.to.shared.u64 t, %1; cvt.u32.u64 %0, t; }" : "=r"(a) : "l"(p));
    return a;
}
__device__ __forceinline__ uint32_t lds32(uint32_t a) {
    uint32_t v;
    asm volatile("ld.shared.b32 %0, [%1];" : "=r"(v) : "r"(a));
    return v;
}
__device__ __forceinline__ void mma16816(float* d, const uint32_t* a, const uint32_t* b) {
    asm volatile(
        "mma.sync.aligned.m16n8k16.row.col.f32.bf16.bf16.f32 "
        "{%0,%1,%2,%3}, {%4,%5,%6,%7}, {%8,%9}, {%0,%1,%2,%3};"
        : "+f"(d[0]), "+f"(d[1]), "+f"(d[2]), "+f"(d[3])
        : "r"(a[0]), "r"(a[1]), "r"(a[2]), "r"(a[3]), "r"(b[0]), "r"(b[1]));
}

__device__ __forceinline__ float sigf(float x) { return 1.f / (1.f + __expf(-x)); }
__device__ __forceinline__ float tanhfast(float x) { return 1.f - 2.f / (__expf(2.f * x) + 1.f); }

// ---------------------------------------------------------------------------
// Split Wh (fp32) -> bf16 hi/lo. Outputs referenced DEVICE-SIDE (bug fix!).
// ---------------------------------------------------------------------------
__global__ __launch_bounds__(256) void split_wh(const float* __restrict__ src) {
    size_t i = (size_t)blockIdx.x * 1024 + (size_t)threadIdx.x * 4;
    float4 w = *(const float4*)(src + i);
    __nv_bfloat16 h0 = __float2bfloat16(w.x), h1 = __float2bfloat16(w.y);
    __nv_bfloat16 h2 = __float2bfloat16(w.z), h3 = __float2bfloat16(w.w);
    *(__nv_bfloat162*)(g_whhi + i)     = __nv_bfloat162(h0, h1);
    *(__nv_bfloat162*)(g_whhi + i + 2) = __nv_bfloat162(h2, h3);
    *(__nv_bfloat162*)(g_whlo + i) =
        __nv_bfloat162(__float2bfloat16(w.x - __bfloat162float(h0)),
                       __float2bfloat16(w.y - __bfloat162float(h1)));
    *(__nv_bfloat162*)(g_whlo + i + 2) =
        __nv_bfloat162(__float2bfloat16(w.z - __bfloat162float(h2)),
                       __float2bfloat16(w.w - __bfloat162float(h3)));
}

// ---------------------------------------------------------------------------
// gx GEMM (fp32, PROVEN in R1)
// ---------------------------------------------------------------------------
__global__ __launch_bounds__(256) void gx_gemm(const float* __restrict__ x,
                                               const float* __restrict__ Wx,
                                               const float* __restrict__ bx,
                                               const float* __restrict__ bh) {
    __shared__ float As[16][64];
    __shared__ float Ws[16][64];
    const int tid = threadIdx.x;
    const int tx = tid & 15, ty = tid >> 4;
    const int m0 = blockIdx.y * 64, n0 = blockIdx.x * 64;
    const int lrow = tid >> 2, lk = (tid & 3) << 2;

    float acc[4][4];
#pragma unroll
    for (int i = 0; i < 4; i++)
#pragma unroll
        for (int j = 0; j < 4; j++) acc[i][j] = 0.f;

    const float* aptr = x + (size_t)(m0 + lrow) * DD + lk;
    const float* wptr = Wx + (size_t)(n0 + lrow) * DD + lk;

    for (int kt = 0; kt < DD; kt += 16) {
        float4 av = *(const float4*)(aptr + kt);
        float4 wv = *(const float4*)(wptr + kt);
        __syncthreads();
        As[lk + 0][lrow] = av.x; As[lk + 1][lrow] = av.y;
        As[lk + 2][lrow] = av.z; As[lk + 3][lrow] = av.w;
        Ws[lk + 0][lrow] = wv.x; Ws[lk + 1][lrow] = wv.y;
        Ws[lk + 2][lrow] = wv.z; Ws[lk + 3][lrow] = wv.w;
        __syncthreads();
#pragma unroll
        for (int kk = 0; kk < 16; kk++) {
            float4 a4 = *(const float4*)&As[kk][ty * 4];
            float4 b4 = *(const float4*)&Ws[kk][tx * 4];
            float a[4] = {a4.x, a4.y, a4.z, a4.w};
            float b[4] = {b4.x, b4.y, b4.z, b4.w};
#pragma unroll
            for (int i = 0; i < 4; i++)
#pragma unroll
                for (int j = 0; j < 4; j++) acc[i][j] = fmaf(a[i], b[j], acc[i][j]);
        }
    }
    const int nb = n0 + tx * 4;
    float4 bias;
    bias.x = bx[nb + 0] + bh[nb + 0];
    bias.y = bx[nb + 1] + bh[nb + 1];
    bias.z = bx[nb + 2] + bh[nb + 2];
    bias.w = bx[nb + 3] + bh[nb + 3];
#pragma unroll
    for (int i = 0; i < 4; i++) {
        const size_t m = (size_t)(m0 + ty * 4 + i);
        float4 v;
        v.x = acc[i][0] + bias.x; v.y = acc[i][1] + bias.y;
        v.z = acc[i][2] + bias.z; v.w = acc[i][3] + bias.w;
        *(float4*)&g_gx[m * GG + nb] = v;
    }
}

// ===========================================================================
// Step kernel (R9 structure): LDG(uint4)->regs->STS staging, double-buffered;
// lds32 fragments + mma (hardware-verified); e2e verify at t=1 + fallback.
// smem buffer (27648 B each, x2), pitch 144 B:
//   Ah[32][72] @0, Al @4608, Bh[64][72] @9216, Bl @18432
// ===========================================================================
#define STEP_BUF 27648
#define STEP_SMEM (2 * STEP_BUF)

struct StFrag {
    uint4 ah[2], al[2], bh[4], bl[4];
};

__device__ __forceinline__ void ldg_chunk(StFrag& f, int tid, int j0, int kc,
                                          const __nv_bfloat16* __restrict__ rh,
                                          const __nv_bfloat16* __restrict__ rl) {
#pragma unroll
    for (int i = 0; i < 2; i++) {
        int idx = tid + 128 * i, row = idx >> 3, k8 = idx & 7;
        size_t go = ((size_t)((row >> 3) * HH + j0 + (row & 7))) * HH
                  + (size_t)kc * 64 + (size_t)k8 * 8;
        f.ah[i] = *(const uint4*)(g_whhi + go);
        f.al[i] = *(const uint4*)(g_whlo + go);
    }
#pragma unroll
    for (int i = 0; i < 4; i++) {
        int idx = tid + 128 * i, b = idx >> 3, k8 = idx & 7;
        size_t go = (size_t)b * HH + (size_t)kc * 64 + (size_t)k8 * 8;
        f.bh[i] = *(const uint4*)(rh + go);
        f.bl[i] = *(const uint4*)(rl + go);
    }
}

__device__ __forceinline__ void sts_chunk(const StFrag& f, char* ab, int tid) {
#pragma unroll
    for (int i = 0; i < 2; i++) {
        int idx = tid + 128 * i, row = idx >> 3, k8 = idx & 7;
        char* d = ab + row * 144 + k8 * 16;
        *(uint4*)(d)        = f.ah[i];
        *(uint4*)(d + 4608) = f.al[i];
    }
#pragma unroll
    for (int i = 0; i < 4; i++) {
        int idx = tid + 128 * i, b = idx >> 3, k8 = idx & 7;
        char* d = ab + 9216 + b * 144 + k8 * 16;
        *(uint4*)(d)        = f.bh[i];
        *(uint4*)(d + 9216) = f.bl[i];
    }
}

// A frag (m16k16): a0=(g,2t..), a1=(g+8,..), a2=(g,2t+8..), a3=(g+8,2t+8..)
__device__ __forceinline__ void loadA(uint32_t base, int r0, int g, uint32_t ka,
                                      uint32_t* a) {
    a[0] = lds32(base + (r0 + g) * 144 + ka);
    a[1] = lds32(base + (r0 + g + 8) * 144 + ka);
    a[2] = lds32(base + (r0 + g) * 144 + ka + 16);
    a[3] = lds32(base + (r0 + g + 8) * 144 + ka + 16);
}
// B frag (k16n8): b0=(k=2t.., n=g), b1=(k=2t+8.., n=g); smem row = n
__device__ __forceinline__ void loadB(uint32_t base, int nb, int g, uint32_t ka,
                                      uint32_t* b) {
    b[0] = lds32(base + (nb + g) * 144 + ka);
    b[1] = lds32(base + (nb + g) * 144 + ka + 16);
}

__device__ __forceinline__ void step_compute(uint32_t sb, int s, int lane, int wid,
                                             float (&acc)[2][2][4]) {
    uint32_t ab = sb + s * STEP_BUF;
    const int g = lane >> 2, tig = lane & 3;
    const uint32_t aB = ab + 9216;
#pragma unroll
    for (int kk = 0; kk < 4; kk++) {
        const uint32_t ka = (uint32_t)((kk * 16 + 2 * tig) * 2);
        uint32_t ah0[4], ah1[4], al0[4], al1[4], bh[2][2], bl[2][2];
        loadA(ab, 0, g, ka, ah0);
        loadA(ab, 16, g, ka, ah1);
        loadA(ab + 4608, 0, g, ka, al0);
        loadA(ab + 4608, 16, g, ka, al1);
        loadB(aB, wid * 16, g, ka, bh[0]);
        loadB(aB, wid * 16 + 8, g, ka, bh[1]);
        loadB(aB + 9216, wid * 16, g, ka, bl[0]);
        loadB(aB + 9216, wid * 16 + 8, g, ka, bl[1]);
        mma16816(acc[0][0], ah0, bh[0]);  mma16816(acc[0][1], ah0, bh[1]);
        mma16816(acc[1][0], ah1, bh[0]);  mma16816(acc[1][1], ah1, bh[1]);
        mma16816(acc[0][0], ah0, bl[0]);  mma16816(acc[0][1], ah0, bl[1]);
        mma16816(acc[1][0], ah1, bl[0]);  mma16816(acc[1][1], ah1, bl[1]);
        mma16816(acc[0][0], al0, bh[0]);  mma16816(acc[0][1], al0, bh[1]);
        mma16816(acc[1][0], al1, bh[0]);  mma16816(acc[1][1], al1, bh[1]);
    }
}

__device__ __forceinline__ void lstm_elem(float* out, int t, int wf, int b, int j,
                                          float iv, float fv, float gv, float ov,
                                          __nv_bfloat16* whp, __nv_bfloat16* wlp) {
    iv = sigf(iv); fv = sigf(fv); gv = tanhfast(gv); ov = sigf(ov);
    const float cp = g_c[b * HH + j];
    const float cn = fmaf(fv, cp, iv * gv);
    const float hn = ov * tanhfast(cn);
    g_c[b * HH + j] = cn;
    out[((size_t)b * SS + t) * HH + j] = hn;
    __nv_bfloat16 hb = __float2bfloat16(hn);
    whp[b * HH + j] = hb;
    wlp[b * HH + j] = __float2bfloat16(hn - __bfloat162float(hb));
    if (wf && t == SS - 1) {
        out[(size_t)BB * SS * HH + (size_t)b * HH + j] = hn;
        out[(size_t)BB * SS * HH + (size_t)BB * HH + (size_t)b * HH + j] = cn;
    }
}

__global__ __launch_bounds__(128) void lstm_step_v10(const float* __restrict__ Wh,
                                                     float* __restrict__ out,
                                                     int t, int wf) {
    const int tid = threadIdx.x;
    const int j0 = blockIdx.x * 8;

    __nv_bfloat16* whp = g_hhi[t & 1];
    __nv_bfloat16* wlp = g_hlo[t & 1];

    if (t == 0) {
        for (int idx = tid; idx < 512; idx += 128) {
            int b = idx >> 3, jl = idx & 7, j = j0 + jl;
            size_t gb = (size_t)b * SS * GG + j;
            float iv = sigf(g_gx[gb]);
            float gv = tanhfast(g_gx[gb + 2 * HH]);
            float ov = sigf(g_gx[gb + 3 * HH]);
            float cn = iv * gv;
            float hn = ov * tanhfast(cn);
            g_c[b * HH + j] = cn;
            out[((size_t)b * SS) * HH + j] = hn;
            __nv_bfloat16 hb = __float2bfloat16(hn);
            whp[b * HH + j] = hb;
            wlp[b * HH + j] = __float2bfloat16(hn - __bfloat162float(hb));
        }
        return;
    }

    extern __shared__ __align__(128) char sm[];
    __shared__ int s_bad;
    const uint32_t sb = smem_u32(sm);
    const int wid = tid >> 5, lane = tid & 31;
    const int g = lane >> 2, q = lane & 3;

    int use_mma = (t == 1) ? 1 : *(volatile int*)&g_mma_ok;

    float acc[2][2][4];
#pragma unroll
    for (int r = 0; r < 2; r++)
#pragma unroll
        for (int c = 0; c < 2; c++)
#pragma unroll
            for (int e = 0; e < 4; e++) acc[r][c][e] = 0.f;

    if (use_mma) {
        const __nv_bfloat16* rh = g_hhi[(t - 1) & 1];
        const __nv_bfloat16* rl = g_hlo[(t - 1) & 1];

        StFrag fr;
        ldg_chunk(fr, tid, j0, 0, rh, rl);
        sts_chunk(fr, sm, tid);
#pragma unroll 1
        for (int kc = 0; kc < 16; kc++) {
            const int s = kc & 1;
            __syncthreads();                 // buf s stores visible CTA-wide
            if (kc < 15) ldg_chunk(fr, tid, j0, kc + 1, rh, rl);  // prefetch
            step_compute(sb, s, lane, wid, acc);
            if (kc < 15) sts_chunk(fr, sm + (s ^ 1) * STEP_BUF, tid);
        }

        if (t == 1) {
            // END-TO-END verify vs fp32 truth from Wh and out[t=0].
            if (tid == 0) s_bad = 0;
            __syncthreads();
            const int j = j0 + g;
            int bc[4];
#pragma unroll
            for (int ci = 0; ci < 4; ci++)
                bc[ci] = wid * 16 + (ci >> 1) * 8 + 2 * q + (ci & 1);
            float ref[4][4];
#pragma unroll
            for (int ga = 0; ga < 4; ga++)
#pragma unroll
                for (int ci = 0; ci < 4; ci++) ref[ga][ci] = 0.f;
            const float* w0 = Wh + (size_t)(0 * HH + j) * HH;
            const float* w1 = Wh + (size_t)(1 * HH + j) * HH;
            const float* w2 = Wh + (size_t)(2 * HH + j) * HH;
            const float* w3 = Wh + (size_t)(3 * HH + j) * HH;
#pragma unroll 4
            for (int k = 0; k < HH; k++) {
                float wv[4] = {w0[k], w1[k], w2[k], w3[k]};
                float hv[4];
#pragma unroll
                for (int ci = 0; ci < 4; ci++)
                    hv[ci] = out[((size_t)bc[ci] * SS + 0) * HH + k];
#pragma unroll
                for (int ga = 0; ga < 4; ga++)
#pragma unroll
                    for (int ci = 0; ci < 4; ci++)
                        ref[ga][ci] = fmaf(wv[ga], hv[ci], ref[ga][ci]);
            }
            bool ok = true;
#pragma unroll
            for (int ga = 0; ga < 4; ga++)
#pragma unroll
                for (int ci = 0; ci < 4; ci++) {
                    float av = acc[ga >> 1][ci >> 1][((ga & 1) << 1) | (ci & 1)];
                    float rv = ref[ga][ci];
                    ok &= fabsf(av - rv) <= (1e-3f + 1e-3f * fabsf(rv));
                }
            if (!ok) s_bad = 1;
            __syncthreads();
            if (s_bad) {
                if (tid == 0) g_mma_ok = 0;
                use_mma = 0;
            }
        }
    }

    if (use_mma) {
        const int j = j0 + g;
        const int n0 = wid * 16;
#pragma unroll
        for (int c = 0; c < 2; c++)
#pragma unroll
            for (int e = 0; e < 2; e++) {
                const int b = n0 + c * 8 + 2 * q + e;
                const size_t gb = ((size_t)b * SS + t) * (size_t)GG + j;
                lstm_elem(out, t, wf, b, j,
                          acc[0][c][e]     + g_gx[gb],
                          acc[0][c][2 + e] + g_gx[gb + HH],
                          acc[1][c][e]     + g_gx[gb + 2 * HH],
                          acc[1][c][2 + e] + g_gx[gb + 3 * HH],
                          whp, wlp);
            }
    } else {
        // fp32 FFMA fallback (independent of staging/mma machinery).
        __syncthreads();
        float* Hs = (float*)sm;                 // [64][132] floats
        const int bq = tid >> 3, jl = tid & 7;
        const int j = j0 + jl;
        float facc[4][4];
#pragma unroll
        for (int a = 0; a < 4; a++)
#pragma unroll
            for (int bz = 0; bz < 4; bz++) facc[a][bz] = 0.f;

#pragma unroll 1
        for (int kt = 0; kt < 8; kt++) {
            __syncthreads();
#pragma unroll
            for (int u = 0; u < 16; u++) {
                int i4 = tid + 128 * u;
                int b = i4 >> 5, k4 = (i4 & 31) << 2;
                float4 hv = *(const float4*)(out + ((size_t)b * SS + (t - 1)) * HH
                                             + kt * 128 + k4);
                *(float4*)&Hs[b * 132 + k4] = hv;
            }
            __syncthreads();
#pragma unroll
            for (int g4 = 0; g4 < 4; g4++) {
                const float* wrow = Wh + (size_t)(g4 * HH + j) * HH + kt * 128;
#pragma unroll 4
                for (int k = 0; k < 128; k += 4) {
                    float4 wv = *(const float4*)(wrow + k);
#pragma unroll
                    for (int bz = 0; bz < 4; bz++) {
                        const float* hp = &Hs[(bq + 16 * bz) * 132 + k];
                        facc[g4][bz] = fmaf(wv.x, hp[0],
                                       fmaf(wv.y, hp[1],
                                       fmaf(wv.z, hp[2],
                                       fmaf(wv.w, hp[3], facc[g4][bz]))));
                    }
                }
            }
        }
#pragma unroll
        for (int bz = 0; bz < 4; bz++) {
            const int b = bq + 16 * bz;
            const size_t gb = ((size_t)b * SS + t) * (size_t)GG + j;
            lstm_elem(out, t, wf, b, j,
                      facc[0][bz] + g_gx[gb],
                      facc[1][bz] + g_gx[gb + HH],
                      facc[2][bz] + g_gx[gb + 2 * HH],
                      facc[3][bz] + g_gx[gb + 3 * HH],
                      whp, wlp);
        }
    }
}

// ---------------------------------------------------------------------------
extern "C" void kernel_launch(void* const* d_in, const int* in_sizes, int n_in,
                              void* d_out, int out_size) {
    const float* x  = (const float*)d_in[0];
    const float* Wx = (const float*)d_in[1];
    const float* Wh = (const float*)d_in[2];
    const float* bx = (const float*)d_in[3];
    const float* bh = (const float*)d_in[4];
    float* out = (float*)d_out;

    const long long full = (long long)BB * SS * HH + 2LL * BB * HH;
    const int wf = ((long long)out_size >= full) ? 1 : 0;

    cudaFuncSetAttribute(lstm_step_v10, cudaFuncAttributeMaxDynamicSharedMemorySize,
                         STEP_SMEM);

    split_wh<<<(GG * HH) / 1024, 256>>>(Wh);   // device-side symbol refs (FIXED)
    gx_gemm<<<dim3(GG / 64, (BB * SS) / 64), 256>>>(x, Wx, bx, bh);
    for (int t = 0; t < SS; t++) {
        lstm_step_v10<<<128, 128, STEP_SMEM>>>(Wh, out, t, wf);
    }
}

// round 11
// speedup vs baseline: 7.9759x; 1.0621x over previous
#include <cuda_runtime.h>
#include <cuda_bf16.h>
#include <math.h>
#include <stdint.h>

#define BB 64
#define SS 512
#define DD 512
#define HH 1024
#define GG 4096   // 4*HH

// ---------------------------------------------------------------------------
// Device-global scratch. NEVER pass these as host-side kernel args (shadow
// symbol bug — found in R10).
// ---------------------------------------------------------------------------
__device__ float g_gx[(size_t)BB * SS * GG];
__device__ __align__(256) __nv_bfloat16 g_whhi[(size_t)GG * HH];
__device__ __align__(256) __nv_bfloat16 g_whlo[(size_t)GG * HH];
__device__ __align__(256) __nv_bfloat16 g_hhi[2][BB * HH];
__device__ __align__(256) __nv_bfloat16 g_hlo[2][BB * HH];
__device__ unsigned g_bar;

// ---------------------------------------------------------------------------
// PTX helpers
// ---------------------------------------------------------------------------
__device__ __forceinline__ uint32_t smem_u32(const void* p) {
    uint32_t a;
    asm("{ .reg .u64 t; cvta.to.shared.u64 t, %1; cvt.u32.u64 %0, t; }" : "=r"(a) : "l"(p));
    return a;
}
__device__ __forceinline__ uint32_t lds32(uint32_t a) {
    uint32_t v;
    asm volatile("ld.shared.b32 %0, [%1];" : "=r"(v) : "r"(a));
    return v;
}
// L2-only load (L1 bypass) — h buffers are cross-CTA coherent only in L2.
__device__ __forceinline__ uint4 ldg_cg(const void* p) {
    uint4 v;
    asm volatile("ld.global.cg.v4.u32 {%0,%1,%2,%3}, [%4];"
                 : "=r"(v.x), "=r"(v.y), "=r"(v.z), "=r"(v.w) : "l"(p));
    return v;
}
__device__ __forceinline__ void mma16816(float* d, const uint32_t* a, const uint32_t* b) {
    asm volatile(
        "mma.sync.aligned.m16n8k16.row.col.f32.bf16.bf16.f32 "
        "{%0,%1,%2,%3}, {%4,%5,%6,%7}, {%8,%9}, {%0,%1,%2,%3};"
        : "+f"(d[0]), "+f"(d[1]), "+f"(d[2]), "+f"(d[3])
        : "r"(a[0]), "r"(a[1]), "r"(a[2]), "r"(a[3]), "r"(b[0]), "r"(b[1]));
}

__device__ __forceinline__ float sigf(float x) { return 1.f / (1.f + __expf(-x)); }
__device__ __forceinline__ float tanhfast(float x) { return 1.f - 2.f / (__expf(2.f * x) + 1.f); }

// Global barrier across 128 co-resident CTAs (wave-1 guaranteed: 128 <= 148).
__device__ __forceinline__ void gbar(int t) {
    __syncthreads();
    if (threadIdx.x == 0) {
        __threadfence();
        atomicAdd(&g_bar, 1u);
        const unsigned target = 128u * (unsigned)(t + 1);
        while (*(volatile unsigned*)&g_bar < target) {}
        __threadfence();
    }
    __syncthreads();
}

// ---------------------------------------------------------------------------
__global__ void bar_reset() { g_bar = 0u; }

// Split Wh (fp32) -> bf16 hi/lo. Device-side symbol refs.
__global__ __launch_bounds__(256) void split_wh(const float* __restrict__ src) {
    size_t i = (size_t)blockIdx.x * 1024 + (size_t)threadIdx.x * 4;
    float4 w = *(const float4*)(src + i);
    __nv_bfloat16 h0 = __float2bfloat16(w.x), h1 = __float2bfloat16(w.y);
    __nv_bfloat16 h2 = __float2bfloat16(w.z), h3 = __float2bfloat16(w.w);
    *(__nv_bfloat162*)(g_whhi + i)     = __nv_bfloat162(h0, h1);
    *(__nv_bfloat162*)(g_whhi + i + 2) = __nv_bfloat162(h2, h3);
    *(__nv_bfloat162*)(g_whlo + i) =
        __nv_bfloat162(__float2bfloat16(w.x - __bfloat162float(h0)),
                       __float2bfloat16(w.y - __bfloat162float(h1)));
    *(__nv_bfloat162*)(g_whlo + i + 2) =
        __nv_bfloat162(__float2bfloat16(w.z - __bfloat162float(h2)),
                       __float2bfloat16(w.w - __bfloat162float(h3)));
}

// ---------------------------------------------------------------------------
// gx GEMM (fp32, proven)
// ---------------------------------------------------------------------------
__global__ __launch_bounds__(256) void gx_gemm(const float* __restrict__ x,
                                               const float* __restrict__ Wx,
                                               const float* __restrict__ bx,
                                               const float* __restrict__ bh) {
    __shared__ float As[16][64];
    __shared__ float Ws[16][64];
    const int tid = threadIdx.x;
    const int tx = tid & 15, ty = tid >> 4;
    const int m0 = blockIdx.y * 64, n0 = blockIdx.x * 64;
    const int lrow = tid >> 2, lk = (tid & 3) << 2;

    float acc[4][4];
#pragma unroll
    for (int i = 0; i < 4; i++)
#pragma unroll
        for (int j = 0; j < 4; j++) acc[i][j] = 0.f;

    const float* aptr = x + (size_t)(m0 + lrow) * DD + lk;
    const float* wptr = Wx + (size_t)(n0 + lrow) * DD + lk;

    for (int kt = 0; kt < DD; kt += 16) {
        float4 av = *(const float4*)(aptr + kt);
        float4 wv = *(const float4*)(wptr + kt);
        __syncthreads();
        As[lk + 0][lrow] = av.x; As[lk + 1][lrow] = av.y;
        As[lk + 2][lrow] = av.z; As[lk + 3][lrow] = av.w;
        Ws[lk + 0][lrow] = wv.x; Ws[lk + 1][lrow] = wv.y;
        Ws[lk + 2][lrow] = wv.z; Ws[lk + 3][lrow] = wv.w;
        __syncthreads();
#pragma unroll
        for (int kk = 0; kk < 16; kk++) {
            float4 a4 = *(const float4*)&As[kk][ty * 4];
            float4 b4 = *(const float4*)&Ws[kk][tx * 4];
            float a[4] = {a4.x, a4.y, a4.z, a4.w};
            float b[4] = {b4.x, b4.y, b4.z, b4.w};
#pragma unroll
            for (int i = 0; i < 4; i++)
#pragma unroll
                for (int j = 0; j < 4; j++) acc[i][j] = fmaf(a[i], b[j], acc[i][j]);
        }
    }
    const int nb = n0 + tx * 4;
    float4 bias;
    bias.x = bx[nb + 0] + bh[nb + 0];
    bias.y = bx[nb + 1] + bh[nb + 1];
    bias.z = bx[nb + 2] + bh[nb + 2];
    bias.w = bx[nb + 3] + bh[nb + 3];
#pragma unroll
    for (int i = 0; i < 4; i++) {
        const size_t m = (size_t)(m0 + ty * 4 + i);
        float4 v;
        v.x = acc[i][0] + bias.x; v.y = acc[i][1] + bias.y;
        v.z = acc[i][2] + bias.z; v.w = acc[i][3] + bias.w;
        *(float4*)&g_gx[m * GG + nb] = v;
    }
}

// ===========================================================================
// PERSISTENT scan kernel: 128 CTAs x 128 thr, all 512 timesteps internal.
// smem map (180 KB):
//   A_hi resident: [0, 73728)        16 chunks x [32 rows][144B pitch]
//   A_lo resident: [73728, 147456)
//   B buffers:     147456 + s*18432  (Bh [64][144] @+0, Bl @+9216)
// ===========================================================================
#define A_LO_OFF 73728
#define B_OFF 147456
#define B_BUF 18432
#define SCAN_SMEM (B_OFF + 2 * B_BUF)   // 184320

struct BFrag { uint4 bh[4], bl[4]; };

__device__ __forceinline__ void ldgB(BFrag& f, int tid, int kc,
                                     const __nv_bfloat16* __restrict__ rh,
                                     const __nv_bfloat16* __restrict__ rl) {
#pragma unroll
    for (int i = 0; i < 4; i++) {
        int idx = tid + 128 * i, b = idx >> 3, k8 = idx & 7;
        size_t go = (size_t)b * HH + (size_t)kc * 64 + (size_t)k8 * 8;
        f.bh[i] = ldg_cg(rh + go);
        f.bl[i] = ldg_cg(rl + go);
    }
}
__device__ __forceinline__ void stsB(const BFrag& f, char* bb, int tid) {
#pragma unroll
    for (int i = 0; i < 4; i++) {
        int idx = tid + 128 * i, b = idx >> 3, k8 = idx & 7;
        char* d = bb + b * 144 + k8 * 16;
        *(uint4*)(d)        = f.bh[i];
        *(uint4*)(d + 9216) = f.bl[i];
    }
}

// A frag (m16k16): a0=(g,2t..), a1=(g+8,..), a2=(g,2t+8..), a3=(g+8,2t+8..)
__device__ __forceinline__ void loadA(uint32_t base, int r0, int g, uint32_t ka,
                                      uint32_t* a) {
    a[0] = lds32(base + (r0 + g) * 144 + ka);
    a[1] = lds32(base + (r0 + g + 8) * 144 + ka);
    a[2] = lds32(base + (r0 + g) * 144 + ka + 16);
    a[3] = lds32(base + (r0 + g + 8) * 144 + ka + 16);
}
__device__ __forceinline__ void loadB(uint32_t base, int nb, int g, uint32_t ka,
                                      uint32_t* b) {
    b[0] = lds32(base + (nb + g) * 144 + ka);
    b[1] = lds32(base + (nb + g) * 144 + ka + 16);
}

__device__ __forceinline__ void compute_chunk(uint32_t sb, int kc, int s,
                                              int lane, int wid,
                                              float (&acc)[2][2][4]) {
    const uint32_t aA = sb + kc * 4608;
    const uint32_t aB = sb + B_OFF + s * B_BUF;
    const int g = lane >> 2, tig = lane & 3;
#pragma unroll
    for (int kk = 0; kk < 4; kk++) {
        const uint32_t ka = (uint32_t)((kk * 16 + 2 * tig) * 2);
        uint32_t ah0[4], ah1[4], al0[4], al1[4], bh[2][2], bl[2][2];
        loadA(aA, 0, g, ka, ah0);
        loadA(aA, 16, g, ka, ah1);
        loadA(aA + A_LO_OFF, 0, g, ka, al0);
        loadA(aA + A_LO_OFF, 16, g, ka, al1);
        loadB(aB, wid * 16, g, ka, bh[0]);
        loadB(aB, wid * 16 + 8, g, ka, bh[1]);
        loadB(aB + 9216, wid * 16, g, ka, bl[0]);
        loadB(aB + 9216, wid * 16 + 8, g, ka, bl[1]);
        mma16816(acc[0][0], ah0, bh[0]);  mma16816(acc[0][1], ah0, bh[1]);
        mma16816(acc[1][0], ah1, bh[0]);  mma16816(acc[1][1], ah1, bh[1]);
        mma16816(acc[0][0], ah0, bl[0]);  mma16816(acc[0][1], ah0, bl[1]);
        mma16816(acc[1][0], ah1, bl[0]);  mma16816(acc[1][1], ah1, bl[1]);
        mma16816(acc[0][0], al0, bh[0]);  mma16816(acc[0][1], al0, bh[1]);
        mma16816(acc[1][0], al1, bh[0]);  mma16816(acc[1][1], al1, bh[1]);
    }
}

__global__ __launch_bounds__(128) void lstm_scan(float* __restrict__ out, int wf) {
    extern __shared__ __align__(128) char sm[];
    const uint32_t sb = smem_u32(sm);
    const int tid = threadIdx.x;
    const int wid = tid >> 5, lane = tid & 31;
    const int g = lane >> 2, q = lane & 3;
    const int j0 = blockIdx.x * 8;

    // ---- Load A tile (Wh hi/lo for this CTA's 32 rows) resident in smem ----
#pragma unroll 1
    for (int kc = 0; kc < 16; kc++) {
#pragma unroll
        for (int i = 0; i < 2; i++) {
            int idx = tid + 128 * i, row = idx >> 3, k8 = idx & 7;
            size_t go = ((size_t)((row >> 3) * HH + j0 + (row & 7))) * HH
                      + (size_t)kc * 64 + (size_t)k8 * 8;
            char* d = sm + kc * 4608 + row * 144 + k8 * 16;
            *(uint4*)(d)            = *(const uint4*)(g_whhi + go);
            *(uint4*)(d + A_LO_OFF) = *(const uint4*)(g_whlo + go);
        }
    }
    __syncthreads();

    // Thread's fixed output set: j = j0 + g, 4 batches.
    const int j = j0 + g;
    int bs[4];
#pragma unroll
    for (int ci = 0; ci < 4; ci++)
        bs[ci] = wid * 16 + (ci >> 1) * 8 + 2 * q + (ci & 1);
    float creg[4];

    // ---- t = 0: gates = gx only ----
    {
        __nv_bfloat16* whp = g_hhi[0];
        __nv_bfloat16* wlp = g_hlo[0];
#pragma unroll
        for (int ci = 0; ci < 4; ci++) {
            const int b = bs[ci];
            const size_t gb = (size_t)b * SS * GG + j;
            float iv = sigf(g_gx[gb]);
            float gv = tanhfast(g_gx[gb + 2 * HH]);
            float ov = sigf(g_gx[gb + 3 * HH]);
            float cn = iv * gv;
            float hn = ov * tanhfast(cn);
            creg[ci] = cn;
            out[(size_t)b * SS * HH + j] = hn;
            __nv_bfloat16 hb = __float2bfloat16(hn);
            whp[b * HH + j] = hb;
            wlp[b * HH + j] = __float2bfloat16(hn - __bfloat162float(hb));
        }
    }
    gbar(0);

    // ---- t = 1 .. 511 ----
#pragma unroll 1
    for (int t = 1; t < SS; t++) {
        const __nv_bfloat16* rh = g_hhi[(t - 1) & 1];
        const __nv_bfloat16* rl = g_hlo[(t - 1) & 1];

        float acc[2][2][4];
#pragma unroll
        for (int r = 0; r < 2; r++)
#pragma unroll
            for (int c = 0; c < 2; c++)
#pragma unroll
                for (int e = 0; e < 4; e++) acc[r][c][e] = 0.f;

        BFrag fr;
        ldgB(fr, tid, 0, rh, rl);
        stsB(fr, sm + B_OFF, tid);
#pragma unroll 1
        for (int kc = 0; kc < 16; kc++) {
            const int s = kc & 1;
            __syncthreads();
            if (kc < 15) ldgB(fr, tid, kc + 1, rh, rl);
            compute_chunk(sb, kc, s, lane, wid, acc);
            if (kc < 15) stsB(fr, sm + B_OFF + (s ^ 1) * B_BUF, tid);
        }

        // Epilogue (c state in registers).
        __nv_bfloat16* whp = g_hhi[t & 1];
        __nv_bfloat16* wlp = g_hlo[t & 1];
#pragma unroll
        for (int c = 0; c < 2; c++)
#pragma unroll
            for (int e = 0; e < 2; e++) {
                const int ci = c * 2 + e;
                const int b = bs[ci];
                const size_t gb = ((size_t)b * SS + t) * (size_t)GG + j;
                float iv = acc[0][c][e]     + g_gx[gb];
                float fv = acc[0][c][2 + e] + g_gx[gb + HH];
                float gv = acc[1][c][e]     + g_gx[gb + 2 * HH];
                float ov = acc[1][c][2 + e] + g_gx[gb + 3 * HH];
                iv = sigf(iv); fv = sigf(fv); gv = tanhfast(gv); ov = sigf(ov);
                const float cn = fmaf(fv, creg[ci], iv * gv);
                const float hn = ov * tanhfast(cn);
                creg[ci] = cn;
                out[((size_t)b * SS + t) * HH + j] = hn;
                __nv_bfloat16 hb = __float2bfloat16(hn);
                whp[b * HH + j] = hb;
                wlp[b * HH + j] = __float2bfloat16(hn - __bfloat162float(hb));
                if (wf && t == SS - 1) {
                    out[(size_t)BB * SS * HH + (size_t)b * HH + j] = hn;
                    out[(size_t)BB * SS * HH + (size_t)BB * HH + (size_t)b * HH + j] = cn;
                }
            }
        gbar(t);
    }
}

// ---------------------------------------------------------------------------
extern "C" void kernel_launch(void* const* d_in, const int* in_sizes, int n_in,
                              void* d_out, int out_size) {
    const float* x  = (const float*)d_in[0];
    const float* Wx = (const float*)d_in[1];
    const float* Wh = (const float*)d_in[2];
    const float* bx = (const float*)d_in[3];
    const float* bh = (const float*)d_in[4];
    float* out = (float*)d_out;

    const long long full = (long long)BB * SS * HH + 2LL * BB * HH;
    const int wf = ((long long)out_size >= full) ? 1 : 0;

    cudaFuncSetAttribute(lstm_scan, cudaFuncAttributeMaxDynamicSharedMemorySize,
                         SCAN_SMEM);

    bar_reset<<<1, 1>>>();
    split_wh<<<(GG * HH) / 1024, 256>>>(Wh);
    gx_gemm<<<dim3(GG / 64, (BB * SS) / 64), 256>>>(x, Wx, bx, bh);
    lstm_scan<<<128, 128, SCAN_SMEM>>>(out, wf);
}

// round 12
// speedup vs baseline: 10.4578x; 1.3112x over previous
#include <cuda_runtime.h>
#include <cuda_bf16.h>
#include <math.h>
#include <stdint.h>

#define BB 64
#define SS 512
#define DD 512
#define HH 1024
#define GG 4096   // 4*HH

// ---------------------------------------------------------------------------
// Device-global scratch. NEVER pass these as host-side kernel args (shadow
// symbol bug — R10 root cause). All kernels reference them device-side.
// ---------------------------------------------------------------------------
__device__ float g_gx[(size_t)BB * SS * GG];
__device__ __align__(256) __nv_bfloat16 g_whhi[(size_t)GG * HH];
__device__ __align__(256) __nv_bfloat16 g_whlo[(size_t)GG * HH];
__device__ __align__(256) __nv_bfloat16 g_wxhi[(size_t)GG * DD];
__device__ __align__(256) __nv_bfloat16 g_wxlo[(size_t)GG * DD];
__device__ __align__(256) __nv_bfloat16 g_xhi[(size_t)BB * SS * DD];
__device__ __align__(256) __nv_bfloat16 g_xlo[(size_t)BB * SS * DD];
__device__ __align__(256) __nv_bfloat16 g_hhi[2][BB * HH];
__device__ __align__(256) __nv_bfloat16 g_hlo[2][BB * HH];
__device__ unsigned g_bar;

// ---------------------------------------------------------------------------
// PTX helpers
// ---------------------------------------------------------------------------
__device__ __forceinline__ uint32_t smem_u32(const void* p) {
    uint32_t a;
    asm("{ .reg .u64 t; cvta.to.shared.u64 t, %1; cvt.u32.u64 %0, t; }" : "=r"(a) : "l"(p));
    return a;
}
__device__ __forceinline__ uint32_t lds32(uint32_t a) {
    uint32_t v;
    asm volatile("ld.shared.b32 %0, [%1];" : "=r"(v) : "r"(a));
    return v;
}
__device__ __forceinline__ uint4 ldg_cg(const void* p) {
    uint4 v;
    asm volatile("ld.global.cg.v4.u32 {%0,%1,%2,%3}, [%4];"
                 : "=r"(v.x), "=r"(v.y), "=r"(v.z), "=r"(v.w) : "l"(p));
    return v;
}
__device__ __forceinline__ void mma16816(float* d, const uint32_t* a, const uint32_t* b) {
    asm volatile(
        "mma.sync.aligned.m16n8k16.row.col.f32.bf16.bf16.f32 "
        "{%0,%1,%2,%3}, {%4,%5,%6,%7}, {%8,%9}, {%0,%1,%2,%3};"
        : "+f"(d[0]), "+f"(d[1]), "+f"(d[2]), "+f"(d[3])
        : "r"(a[0]), "r"(a[1]), "r"(a[2]), "r"(a[3]), "r"(b[0]), "r"(b[1]));
}

__device__ __forceinline__ float sigf(float x) { return 1.f / (1.f + __expf(-x)); }
__device__ __forceinline__ float tanhfast(float x) { return 1.f - 2.f / (__expf(2.f * x) + 1.f); }

// Global barrier across 128 co-resident CTAs.
__device__ __forceinline__ void gbar(int t) {
    __syncthreads();
    if (threadIdx.x == 0) {
        __threadfence();
        atomicAdd(&g_bar, 1u);
        const unsigned target = 128u * (unsigned)(t + 1);
        while (*(volatile unsigned*)&g_bar < target) {}
        __threadfence();
    }
    __syncthreads();
}

__global__ void bar_reset() { g_bar = 0u; }

// ---------------------------------------------------------------------------
// Splits (device-symbol writes ONLY; src via harness pointer)
// ---------------------------------------------------------------------------
__device__ __forceinline__ void split4(const float* src, size_t i,
                                       __nv_bfloat16* hi, __nv_bfloat16* lo) {
    float4 w = *(const float4*)(src + i);
    __nv_bfloat16 h0 = __float2bfloat16(w.x), h1 = __float2bfloat16(w.y);
    __nv_bfloat16 h2 = __float2bfloat16(w.z), h3 = __float2bfloat16(w.w);
    *(__nv_bfloat162*)(hi + i)     = __nv_bfloat162(h0, h1);
    *(__nv_bfloat162*)(hi + i + 2) = __nv_bfloat162(h2, h3);
    *(__nv_bfloat162*)(lo + i) =
        __nv_bfloat162(__float2bfloat16(w.x - __bfloat162float(h0)),
                       __float2bfloat16(w.y - __bfloat162float(h1)));
    *(__nv_bfloat162*)(lo + i + 2) =
        __nv_bfloat162(__float2bfloat16(w.z - __bfloat162float(h2)),
                       __float2bfloat16(w.w - __bfloat162float(h3)));
}
__global__ __launch_bounds__(256) void split_wh(const float* __restrict__ src) {
    split4(src, (size_t)blockIdx.x * 1024 + (size_t)threadIdx.x * 4, g_whhi, g_whlo);
}
__global__ __launch_bounds__(256) void split_wx(const float* __restrict__ src) {
    split4(src, (size_t)blockIdx.x * 1024 + (size_t)threadIdx.x * 4, g_wxhi, g_wxlo);
}
__global__ __launch_bounds__(256) void split_x(const float* __restrict__ src) {
    split4(src, (size_t)blockIdx.x * 1024 + (size_t)threadIdx.x * 4, g_xhi, g_xlo);
}

// ---------------------------------------------------------------------------
// Fragment loaders (HARDWARE-PROVEN mapping; pitch parametrized)
// A frag (m16k16): a0=(g,2t..), a1=(g+8,..), a2=(g,2t+8..), a3=(g+8,2t+8..)
// ---------------------------------------------------------------------------
__device__ __forceinline__ void loadA_p(uint32_t base, int r0, int g, uint32_t ka,
                                        int pitch, uint32_t* a) {
    a[0] = lds32(base + (r0 + g) * pitch + ka);
    a[1] = lds32(base + (r0 + g + 8) * pitch + ka);
    a[2] = lds32(base + (r0 + g) * pitch + ka + 16);
    a[3] = lds32(base + (r0 + g + 8) * pitch + ka + 16);
}
__device__ __forceinline__ void loadB_p(uint32_t base, int nb, int g, uint32_t ka,
                                        int pitch, uint32_t* b) {
    b[0] = lds32(base + (nb + g) * pitch + ka);
    b[1] = lds32(base + (nb + g) * pitch + ka + 16);
}

// ===========================================================================
// gx GEMM via mma: g_gx[m][n] = xhat[m,:].Wxhat[n,:] (3-pass hi/lo) + bias
//   CTA 128(m) x 128(n), 256 thr, 8 warps (wr=wid&3 -> m32, wc=wid>>2 -> n64).
//   K=512 in 16 chunks of 32; pitch 80 B; LDG->regs->STS double buffer.
// smem buffer (40960 B each, x2): Xh @0, Xl @10240, Wh @20480, Wl @30720
// ===========================================================================
#define GXB 40960
#define GX_SMEM (2 * GXB)

struct GxFrag { uint4 xh[2], xl[2], wh[2], wl[2]; };

__device__ __forceinline__ void gx_ldg(GxFrag& f, int tid, int m0, int n0, int kc) {
#pragma unroll
    for (int i = 0; i < 2; i++) {
        int idx = tid + 256 * i, row = idx >> 2, k8 = idx & 3;
        size_t gox = (size_t)(m0 + row) * DD + (size_t)kc * 32 + (size_t)k8 * 8;
        size_t gow = (size_t)(n0 + row) * DD + (size_t)kc * 32 + (size_t)k8 * 8;
        f.xh[i] = *(const uint4*)(g_xhi + gox);
        f.xl[i] = *(const uint4*)(g_xlo + gox);
        f.wh[i] = *(const uint4*)(g_wxhi + gow);
        f.wl[i] = *(const uint4*)(g_wxlo + gow);
    }
}
__device__ __forceinline__ void gx_sts(const GxFrag& f, char* ab, int tid) {
#pragma unroll
    for (int i = 0; i < 2; i++) {
        int idx = tid + 256 * i, row = idx >> 2, k8 = idx & 3;
        char* d = ab + row * 80 + k8 * 16;
        *(uint4*)(d)         = f.xh[i];
        *(uint4*)(d + 10240) = f.xl[i];
        *(uint4*)(d + 20480) = f.wh[i];
        *(uint4*)(d + 30720) = f.wl[i];
    }
}

__device__ __forceinline__ void gx_compute(uint32_t ab, int lane, int wr, int wc,
                                           float (&acc)[2][8][4]) {
    const int g = lane >> 2, tig = lane & 3;
#pragma unroll
    for (int kk = 0; kk < 2; kk++) {
        const uint32_t ka = (uint32_t)((kk * 16 + 2 * tig) * 2);
        uint32_t ah0[4], ah1[4], al0[4], al1[4];
        loadA_p(ab, wr * 32, g, ka, 80, ah0);
        loadA_p(ab, wr * 32 + 16, g, ka, 80, ah1);
        loadA_p(ab + 10240, wr * 32, g, ka, 80, al0);
        loadA_p(ab + 10240, wr * 32 + 16, g, ka, 80, al1);
#pragma unroll
        for (int ng = 0; ng < 8; ng++) {
            uint32_t bh[2], bl[2];
            loadB_p(ab + 20480, wc * 64 + ng * 8, g, ka, 80, bh);
            loadB_p(ab + 30720, wc * 64 + ng * 8, g, ka, 80, bl);
            mma16816(acc[0][ng], ah0, bh);
            mma16816(acc[1][ng], ah1, bh);
            mma16816(acc[0][ng], ah0, bl);
            mma16816(acc[1][ng], ah1, bl);
            mma16816(acc[0][ng], al0, bh);
            mma16816(acc[1][ng], al1, bh);
        }
    }
}

__global__ __launch_bounds__(256) void gx_mma(const float* __restrict__ bx,
                                              const float* __restrict__ bh) {
    extern __shared__ __align__(128) char sm[];
    const uint32_t sb = smem_u32(sm);
    const int tid = threadIdx.x;
    const int wid = tid >> 5, lane = tid & 31;
    const int wr = wid & 3, wc = wid >> 2;
    const int m0 = blockIdx.y * 128, n0 = blockIdx.x * 128;

    float acc[2][8][4];
#pragma unroll
    for (int r = 0; r < 2; r++)
#pragma unroll
        for (int c = 0; c < 8; c++)
#pragma unroll
            for (int e = 0; e < 4; e++) acc[r][c][e] = 0.f;

    GxFrag fr;
    gx_ldg(fr, tid, m0, n0, 0);
    gx_sts(fr, sm, tid);
#pragma unroll 1
    for (int kc = 0; kc < 16; kc++) {
        const int s = kc & 1;
        __syncthreads();
        if (kc < 15) gx_ldg(fr, tid, m0, n0, kc + 1);
        gx_compute(sb + s * GXB, lane, wr, wc, acc);
        if (kc < 15) gx_sts(fr, sm + (s ^ 1) * GXB, tid);
    }

    // Epilogue (proven D map): c0/c1=(row g, col 2t/2t+1), c2/c3=(row g+8, ·)
    const int r0 = m0 + wr * 32 + (lane >> 2);
    const int c0 = n0 + wc * 64 + 2 * (lane & 3);
#pragma unroll
    for (int ng = 0; ng < 8; ng++) {
        const int n = c0 + ng * 8;
        const float b0 = bx[n] + bh[n];
        const float b1 = bx[n + 1] + bh[n + 1];
#pragma unroll
        for (int rg = 0; rg < 2; rg++) {
            const int m = r0 + rg * 16;
            *(float2*)&g_gx[(size_t)m * GG + n] =
                make_float2(acc[rg][ng][0] + b0, acc[rg][ng][1] + b1);
            *(float2*)&g_gx[(size_t)(m + 8) * GG + n] =
                make_float2(acc[rg][ng][2] + b0, acc[rg][ng][3] + b1);
        }
    }
}

// ===========================================================================
// PERSISTENT scan kernel (unchanged from R11, proven)
// ===========================================================================
#define A_LO_OFF 73728
#define B_OFF 147456
#define B_BUF 18432
#define SCAN_SMEM (B_OFF + 2 * B_BUF)   // 184320

struct BFrag { uint4 bh[4], bl[4]; };

__device__ __forceinline__ void ldgB(BFrag& f, int tid, int kc,
                                     const __nv_bfloat16* __restrict__ rh,
                                     const __nv_bfloat16* __restrict__ rl) {
#pragma unroll
    for (int i = 0; i < 4; i++) {
        int idx = tid + 128 * i, b = idx >> 3, k8 = idx & 7;
        size_t go = (size_t)b * HH + (size_t)kc * 64 + (size_t)k8 * 8;
        f.bh[i] = ldg_cg(rh + go);
        f.bl[i] = ldg_cg(rl + go);
    }
}
__device__ __forceinline__ void stsB(const BFrag& f, char* bb, int tid) {
#pragma unroll
    for (int i = 0; i < 4; i++) {
        int idx = tid + 128 * i, b = idx >> 3, k8 = idx & 7;
        char* d = bb + b * 144 + k8 * 16;
        *(uint4*)(d)        = f.bh[i];
        *(uint4*)(d + 9216) = f.bl[i];
    }
}

__device__ __forceinline__ void compute_chunk(uint32_t sb, int kc, int s,
                                              int lane, int wid,
                                              float (&acc)[2][2][4]) {
    const uint32_t aA = sb + kc * 4608;
    const uint32_t aB = sb + B_OFF + s * B_BUF;
    const int g = lane >> 2, tig = lane & 3;
#pragma unroll
    for (int kk = 0; kk < 4; kk++) {
        const uint32_t ka = (uint32_t)((kk * 16 + 2 * tig) * 2);
        uint32_t ah0[4], ah1[4], al0[4], al1[4], bh[2][2], bl[2][2];
        loadA_p(aA, 0, g, ka, 144, ah0);
        loadA_p(aA, 16, g, ka, 144, ah1);
        loadA_p(aA + A_LO_OFF, 0, g, ka, 144, al0);
        loadA_p(aA + A_LO_OFF, 16, g, ka, 144, al1);
        loadB_p(aB, wid * 16, g, ka, 144, bh[0]);
        loadB_p(aB, wid * 16 + 8, g, ka, 144, bh[1]);
        loadB_p(aB + 9216, wid * 16, g, ka, 144, bl[0]);
        loadB_p(aB + 9216, wid * 16 + 8, g, ka, 144, bl[1]);
        mma16816(acc[0][0], ah0, bh[0]);  mma16816(acc[0][1], ah0, bh[1]);
        mma16816(acc[1][0], ah1, bh[0]);  mma16816(acc[1][1], ah1, bh[1]);
        mma16816(acc[0][0], ah0, bl[0]);  mma16816(acc[0][1], ah0, bl[1]);
        mma16816(acc[1][0], ah1, bl[0]);  mma16816(acc[1][1], ah1, bl[1]);
        mma16816(acc[0][0], al0, bh[0]);  mma16816(acc[0][1], al0, bh[1]);
        mma16816(acc[1][0], al1, bh[0]);  mma16816(acc[1][1], al1, bh[1]);
    }
}

__global__ __launch_bounds__(128) void lstm_scan(float* __restrict__ out, int wf) {
    extern __shared__ __align__(128) char sm[];
    const uint32_t sb = smem_u32(sm);
    const int tid = threadIdx.x;
    const int wid = tid >> 5, lane = tid & 31;
    const int g = lane >> 2, q = lane & 3;
    const int j0 = blockIdx.x * 8;

    // A tile (Wh hi/lo, this CTA's 32 rows) resident in smem.
#pragma unroll 1
    for (int kc = 0; kc < 16; kc++) {
#pragma unroll
        for (int i = 0; i < 2; i++) {
            int idx = tid + 128 * i, row = idx >> 3, k8 = idx & 7;
            size_t go = ((size_t)((row >> 3) * HH + j0 + (row & 7))) * HH
                      + (size_t)kc * 64 + (size_t)k8 * 8;
            char* d = sm + kc * 4608 + row * 144 + k8 * 16;
            *(uint4*)(d)            = *(const uint4*)(g_whhi + go);
            *(uint4*)(d + A_LO_OFF) = *(const uint4*)(g_whlo + go);
        }
    }
    __syncthreads();

    const int j = j0 + g;
    int bs[4];
#pragma unroll
    for (int ci = 0; ci < 4; ci++)
        bs[ci] = wid * 16 + (ci >> 1) * 8 + 2 * q + (ci & 1);
    float creg[4];

    // t = 0
    {
        __nv_bfloat16* whp = g_hhi[0];
        __nv_bfloat16* wlp = g_hlo[0];
#pragma unroll
        for (int ci = 0; ci < 4; ci++) {
            const int b = bs[ci];
            const size_t gb = (size_t)b * SS * GG + j;
            float iv = sigf(g_gx[gb]);
            float gv = tanhfast(g_gx[gb + 2 * HH]);
            float ov = sigf(g_gx[gb + 3 * HH]);
            float cn = iv * gv;
            float hn = ov * tanhfast(cn);
            creg[ci] = cn;
            out[(size_t)b * SS * HH + j] = hn;
            __nv_bfloat16 hb = __float2bfloat16(hn);
            whp[b * HH + j] = hb;
            wlp[b * HH + j] = __float2bfloat16(hn - __bfloat162float(hb));
        }
    }
    gbar(0);

    // t = 1 .. 511
#pragma unroll 1
    for (int t = 1; t < SS; t++) {
        const __nv_bfloat16* rh = g_hhi[(t - 1) & 1];
        const __nv_bfloat16* rl = g_hlo[(t - 1) & 1];

        float acc[2][2][4];
#pragma unroll
        for (int r = 0; r < 2; r++)
#pragma unroll
            for (int c = 0; c < 2; c++)
#pragma unroll
                for (int e = 0; e < 4; e++) acc[r][c][e] = 0.f;

        BFrag fr;
        ldgB(fr, tid, 0, rh, rl);
        stsB(fr, sm + B_OFF, tid);
#pragma unroll 1
        for (int kc = 0; kc < 16; kc++) {
            const int s = kc & 1;
            __syncthreads();
            if (kc < 15) ldgB(fr, tid, kc + 1, rh, rl);
            compute_chunk(sb, kc, s, lane, wid, acc);
            if (kc < 15) stsB(fr, sm + B_OFF + (s ^ 1) * B_BUF, tid);
        }

        __nv_bfloat16* whp = g_hhi[t & 1];
        __nv_bfloat16* wlp = g_hlo[t & 1];
#pragma unroll
        for (int c = 0; c < 2; c++)
#pragma unroll
            for (int e = 0; e < 2; e++) {
                const int ci = c * 2 + e;
                const int b = bs[ci];
                const size_t gb = ((size_t)b * SS + t) * (size_t)GG + j;
                float iv = acc[0][c][e]     + g_gx[gb];
                float fv = acc[0][c][2 + e] + g_gx[gb + HH];
                float gv = acc[1][c][e]     + g_gx[gb + 2 * HH];
                float ov = acc[1][c][2 + e] + g_gx[gb + 3 * HH];
                iv = sigf(iv); fv = sigf(fv); gv = tanhfast(gv); ov = sigf(ov);
                const float cn = fmaf(fv, creg[ci], iv * gv);
                const float hn = ov * tanhfast(cn);
                creg[ci] = cn;
                out[((size_t)b * SS + t) * HH + j] = hn;
                __nv_bfloat16 hb = __float2bfloat16(hn);
                whp[b * HH + j] = hb;
                wlp[b * HH + j] = __float2bfloat16(hn - __bfloat162float(hb));
                if (wf && t == SS - 1) {
                    out[(size_t)BB * SS * HH + (size_t)b * HH + j] = hn;
                    out[(size_t)BB * SS * HH + (size_t)BB * HH + (size_t)b * HH + j] = cn;
                }
            }
        gbar(t);
    }
}

// ---------------------------------------------------------------------------
extern "C" void kernel_launch(void* const* d_in, const int* in_sizes, int n_in,
                              void* d_out, int out_size) {
    const float* x  = (const float*)d_in[0];
    const float* Wx = (const float*)d_in[1];
    const float* Wh = (const float*)d_in[2];
    const float* bx = (const float*)d_in[3];
    const float* bh = (const float*)d_in[4];
    float* out = (float*)d_out;

    const long long full = (long long)BB * SS * HH + 2LL * BB * HH;
    const int wf = ((long long)out_size >= full) ? 1 : 0;

    cudaFuncSetAttribute(lstm_scan, cudaFuncAttributeMaxDynamicSharedMemorySize,
                         SCAN_SMEM);
    cudaFuncSetAttribute(gx_mma, cudaFuncAttributeMaxDynamicSharedMemorySize,
                         GX_SMEM);

    bar_reset<<<1, 1>>>();
    split_wh<<<(GG * HH) / 1024, 256>>>(Wh);
    split_wx<<<(GG * DD) / 1024, 256>>>(Wx);
    split_x<<<(BB * SS * DD) / 1024, 256>>>(x);
    gx_mma<<<dim3(GG / 128, (BB * SS) / 128), 256, GX_SMEM>>>(bx, bh);
    lstm_scan<<<128, 128, SCAN_SMEM>>>(out, wf);
}